// round 5
// baseline (speedup 1.0000x reference)
#include <cuda_runtime.h>
#include <cuda_bf16.h>

#define TT 4096
#define DD 1024
#define FF 4096
#define EE 8
#define NROWS (TT * 2)
#define NW   (EE * FF * DD)

typedef unsigned int u32;

// ================= device scratch (static) =================
__device__ __nv_bfloat16 g_xhi[TT * DD], g_xlo[TT * DD];
__device__ __nv_bfloat16 g_w1hi[NW], g_w1lo[NW];
__device__ __nv_bfloat16 g_w3hi[NW], g_w3lo[NW];
__device__ __nv_bfloat16 g_w2hi[NW], g_w2lo[NW];
__device__ __nv_bfloat16 g_acthi[(size_t)NROWS * FF], g_actlo[(size_t)NROWS * FF];

__device__ int   g_tokExp[TT * 2];
__device__ float g_tokW[TT * 2];
__device__ int   g_count[EE];
__device__ int   g_offset[EE];
__device__ int   g_cursor[EE];
__device__ int   g_rowTok[NROWS];
__device__ float g_rowW[NROWS];

// ================= PTX helpers (sm_80-generic only) =================
__device__ __forceinline__ u32 smem_u32(const void* p) {
    u32 a;
    asm("{ .reg .u64 t; cvta.to.shared.u64 t, %1; cvt.u32.u64 %0, t; }" : "=r"(a) : "l"(p));
    return a;
}
__device__ __forceinline__ void cp16(u32 dst, const void* src) {
    asm volatile("cp.async.cg.shared.global [%0], [%1], 16;" :: "r"(dst), "l"(src));
}
__device__ __forceinline__ void cp_commit() {
    asm volatile("cp.async.commit_group;" ::: "memory");
}
__device__ __forceinline__ void cp_wait1() {
    asm volatile("cp.async.wait_group 1;" ::: "memory");
}
__device__ __forceinline__ void ldsm4(u32 addr, u32* r) {
    asm volatile("ldmatrix.sync.aligned.m8n8.x4.shared.b16 {%0,%1,%2,%3}, [%4];"
        : "=r"(r[0]), "=r"(r[1]), "=r"(r[2]), "=r"(r[3]) : "r"(addr));
}
__device__ __forceinline__ void mma16816(float* d, const u32* a, const u32* b) {
    asm volatile(
        "mma.sync.aligned.m16n8k16.row.col.f32.bf16.bf16.f32 "
        "{%0,%1,%2,%3}, {%4,%5,%6,%7}, {%8,%9}, {%0,%1,%2,%3};"
        : "+f"(d[0]), "+f"(d[1]), "+f"(d[2]), "+f"(d[3])
        : "r"(a[0]), "r"(a[1]), "r"(a[2]), "r"(a[3]), "r"(b[0]), "r"(b[1]));
}

#define KT     32
#define PITCH  40                     // bf16 elems per smem row (80B: conflict-free)
#define ROWB   (PITCH * 2)            // 80 bytes per row
#define TILE128 (128 * ROWB)          // 10240 B
#define TILE64  (64 * ROWB)           // 5120 B
#define TILE256 (256 * ROWB)          // 20480 B

// ================= fused split (+reset) =================
#define XC  (TT * DD / 4)
#define WC  (NW / 4)
__global__ void __launch_bounds__(256)
split_all_kernel(const float* __restrict__ x,  const float* __restrict__ w1,
                 const float* __restrict__ w3, const float* __restrict__ w2) {
    if (blockIdx.x == 0 && threadIdx.x < EE) g_count[threadIdx.x] = 0;
    size_t i = (size_t)blockIdx.x * 256 + threadIdx.x;
    const float* src;
    __nv_bfloat16 *hi, *lo;
    if (i < XC)               { src = x;  hi = g_xhi;  lo = g_xlo; }
    else if (i < XC + WC)     { src = w1; hi = g_w1hi; lo = g_w1lo; i -= XC; }
    else if (i < XC + 2 * WC) { src = w3; hi = g_w3hi; lo = g_w3lo; i -= XC + WC; }
    else if (i < XC + 3 * WC) { src = w2; hi = g_w2hi; lo = g_w2lo; i -= XC + 2 * WC; }
    else return;
    float4 v = ((const float4*)src)[i];
    __nv_bfloat162 h01, h23, l01, l23;
    h01.x = __float2bfloat16(v.x); l01.x = __float2bfloat16(v.x - __bfloat162float(h01.x));
    h01.y = __float2bfloat16(v.y); l01.y = __float2bfloat16(v.y - __bfloat162float(h01.y));
    h23.x = __float2bfloat16(v.z); l23.x = __float2bfloat16(v.z - __bfloat162float(h23.x));
    h23.y = __float2bfloat16(v.w); l23.y = __float2bfloat16(v.w - __bfloat162float(h23.y));
    ((uint2*)hi)[i] = make_uint2(*(u32*)&h01, *(u32*)&h23);
    ((uint2*)lo)[i] = make_uint2(*(u32*)&l01, *(u32*)&l23);
}

// ================= router =================
__global__ void router_kernel(const float* __restrict__ x,
                              const float* __restrict__ gw,
                              const float* __restrict__ gb) {
    const int t = blockIdx.x, tid = threadIdx.x;
    float acc[EE];
#pragma unroll
    for (int e = 0; e < EE; e++) acc[e] = 0.f;
    const float* xr = x + (size_t)t * DD;
    for (int d = tid; d < DD; d += 128) {
        float xv = xr[d];
#pragma unroll
        for (int e = 0; e < EE; e++) acc[e] += xv * gw[e * DD + d];
    }
    __shared__ float red[EE][128];
#pragma unroll
    for (int e = 0; e < EE; e++) red[e][tid] = acc[e];
    __syncthreads();
    for (int s = 64; s > 0; s >>= 1) {
        if (tid < s) {
#pragma unroll
            for (int e = 0; e < EE; e++) red[e][tid] += red[e][tid + s];
        }
        __syncthreads();
    }
    if (tid == 0) {
        float lg[EE]; float mx = -1e30f;
#pragma unroll
        for (int e = 0; e < EE; e++) { lg[e] = red[e][0] + gb[e]; mx = fmaxf(mx, lg[e]); }
#pragma unroll
        for (int e = 0; e < EE; e++) lg[e] = expf(lg[e] - mx);
        int i1 = 0;
#pragma unroll
        for (int e = 1; e < EE; e++) if (lg[e] > lg[i1]) i1 = e;
        int i2 = (i1 == 0) ? 1 : 0;
#pragma unroll
        for (int e = 0; e < EE; e++) if (e != i2 && e != i1 && lg[e] > lg[i2]) i2 = e;
        float p1 = lg[i1], p2 = lg[i2], inv = 1.f / (p1 + p2);
        g_tokExp[t * 2 + 0] = i1; g_tokW[t * 2 + 0] = p1 * inv;
        g_tokExp[t * 2 + 1] = i2; g_tokW[t * 2 + 1] = p2 * inv;
        atomicAdd(&g_count[i1], 1);
        atomicAdd(&g_count[i2], 1);
    }
}

// ================= fused scan + scatter (single block) =================
__global__ void scanscatter_kernel() {
    const int tid = threadIdx.x;
    if (tid == 0) {
        int off = 0;
#pragma unroll
        for (int e = 0; e < EE; e++) { g_offset[e] = off; g_cursor[e] = off; off += g_count[e]; }
    }
    __syncthreads();
    for (int t = tid; t < TT; t += 256) {
#pragma unroll
        for (int s = 0; s < 2; s++) {
            int e = g_tokExp[t * 2 + s];
            int p = atomicAdd(&g_cursor[e], 1);
            g_rowTok[p] = t;
            g_rowW[p]   = g_tokW[t * 2 + s];
        }
    }
}

// ================= GEMM1: block 256x64, warp tile 64x32 dual, bf16x3 ==========
// stage: Ahi(256r) Alo(256r) w1h(64r) w1l w3h w3l = 2*20480 + 4*5120 = 61440
#define G1_STAGE (2 * TILE256 + 4 * TILE64)
#define G1_SMEM  (1024 + 3 * G1_STAGE)     // 185344

__global__ void __launch_bounds__(256, 1)
gemm1_mma() {
    extern __shared__ char smem[];
    const int e   = blockIdx.z;
    const int cnt = g_count[e];
    const int off = g_offset[e];
    const int mB  = blockIdx.y * 256;
    if (mB >= cnt) return;
    const int valid = min(256, cnt - mB);
    const int nf0   = blockIdx.x * 64;
    const int tid   = threadIdx.x;
    const int wid   = tid >> 5, lane = tid & 31;

    int* tokSm = (int*)smem;
    if (tid < 256) tokSm[tid] = g_rowTok[off + mB + min(tid, valid - 1)];
    __syncthreads();

    const u32 sb = smem_u32(smem);
    const size_t wbase = (size_t)e * FF * DD + (size_t)nf0 * DD;

    const int lrow = tid >> 2, lch = tid & 3;    // lrow 0..63
    const int tok0 = tokSm[lrow], tok1 = tokSm[lrow + 64];
    const int tok2 = tokSm[lrow + 128], tok3 = tokSm[lrow + 192];

    auto load_stage = [&](int s, int k0) {
        u32 st = sb + 1024 + s * G1_STAGE;
        const u32 co = (u32)(lrow * ROWB + lch * 16);
        const size_t ko = (size_t)(k0 + lch * 8);
        // A: 4 row groups, hi+lo
        cp16(st + co,                       &g_xhi[(size_t)tok0 * DD + ko]);
        cp16(st + co + 64 * ROWB,           &g_xhi[(size_t)tok1 * DD + ko]);
        cp16(st + co + 128 * ROWB,          &g_xhi[(size_t)tok2 * DD + ko]);
        cp16(st + co + 192 * ROWB,          &g_xhi[(size_t)tok3 * DD + ko]);
        cp16(st + TILE256 + co,             &g_xlo[(size_t)tok0 * DD + ko]);
        cp16(st + TILE256 + co + 64 * ROWB, &g_xlo[(size_t)tok1 * DD + ko]);
        cp16(st + TILE256 + co + 128 * ROWB,&g_xlo[(size_t)tok2 * DD + ko]);
        cp16(st + TILE256 + co + 192 * ROWB,&g_xlo[(size_t)tok3 * DD + ko]);
        // B: 64 rows x 4 arrays
        const size_t go = wbase + (size_t)lrow * DD + ko;
        const u32 bb = st + 2 * TILE256;
        cp16(bb + co,               &g_w1hi[go]);
        cp16(bb + TILE64 + co,      &g_w1lo[go]);
        cp16(bb + 2 * TILE64 + co,  &g_w3hi[go]);
        cp16(bb + 3 * TILE64 + co,  &g_w3lo[go]);
    };

    // warps: 4m x 2n, warp tile 64x32
    const int m_w = (wid >> 1) * 64, n_w = (wid & 1) * 32;
    const int lmat = lane >> 3, lr = lane & 7;
    const int aRow = m_w + (lmat & 1) * 8 + lr;
    const int aCol = (lmat >> 1) * 8;
    const int bRow = n_w + (lmat >> 1) * 8 + lr;
    const int bCol = (lmat & 1) * 8;

    float acc1[4][4][4], acc2[4][4][4];
#pragma unroll
    for (int mt = 0; mt < 4; mt++)
#pragma unroll
        for (int nt = 0; nt < 4; nt++)
#pragma unroll
            for (int q = 0; q < 4; q++) { acc1[mt][nt][q] = 0.f; acc2[mt][nt][q] = 0.f; }

    load_stage(0, 0);  cp_commit();
    load_stage(1, KT); cp_commit();

    const int NK = DD / KT;   // 32
    for (int kt = 0; kt < NK; kt++) {
        cp_wait1();
        __syncthreads();
        if (kt + 2 < NK) load_stage((kt + 2) % 3, (kt + 2) * KT);
        cp_commit();
        const u32 st = sb + 1024 + (kt % 3) * G1_STAGE;
        const u32 bb = st + 2 * TILE256;
#pragma unroll
        for (int k16 = 0; k16 < KT; k16 += 16) {
            u32 aH[4][4], aL[4][4];
#pragma unroll
            for (int mt = 0; mt < 4; mt++) {
                u32 ao = (u32)((aRow + mt * 16) * PITCH + k16 + aCol) * 2;
                ldsm4(st + ao, aH[mt]);
                ldsm4(st + TILE256 + ao, aL[mt]);
            }
#pragma unroll
            for (int p = 0; p < 2; p++) {
                u32 bo = (u32)((bRow + p * 16) * PITCH + k16 + bCol) * 2;
                u32 b1h[4], b1l[4], b3h[4], b3l[4];
                ldsm4(bb + bo,              b1h);
                ldsm4(bb + TILE64 + bo,     b1l);
                ldsm4(bb + 2 * TILE64 + bo, b3h);
                ldsm4(bb + 3 * TILE64 + bo, b3l);
                // term-major: breaks accumulator RAW chains (reuse distance 16)
#pragma unroll
                for (int mt = 0; mt < 4; mt++)
#pragma unroll
                    for (int q = 0; q < 2; q++)
                        mma16816(acc1[mt][p * 2 + q], aH[mt], &b1h[q * 2]);
#pragma unroll
                for (int mt = 0; mt < 4; mt++)
#pragma unroll
                    for (int q = 0; q < 2; q++)
                        mma16816(acc2[mt][p * 2 + q], aH[mt], &b3h[q * 2]);
#pragma unroll
                for (int mt = 0; mt < 4; mt++)
#pragma unroll
                    for (int q = 0; q < 2; q++)
                        mma16816(acc1[mt][p * 2 + q], aH[mt], &b1l[q * 2]);
#pragma unroll
                for (int mt = 0; mt < 4; mt++)
#pragma unroll
                    for (int q = 0; q < 2; q++)
                        mma16816(acc2[mt][p * 2 + q], aH[mt], &b3l[q * 2]);
#pragma unroll
                for (int mt = 0; mt < 4; mt++)
#pragma unroll
                    for (int q = 0; q < 2; q++)
                        mma16816(acc1[mt][p * 2 + q], aL[mt], &b1h[q * 2]);
#pragma unroll
                for (int mt = 0; mt < 4; mt++)
#pragma unroll
                    for (int q = 0; q < 2; q++)
                        mma16816(acc2[mt][p * 2 + q], aL[mt], &b3h[q * 2]);
            }
        }
        __syncthreads();
    }

    // epilogue: silu(h1)*h3 -> bf16 hi/lo -> global
    u32* outHi = (u32*)g_acthi;
    u32* outLo = (u32*)g_actlo;
#pragma unroll
    for (int mt = 0; mt < 4; mt++)
#pragma unroll
        for (int rh = 0; rh < 2; rh++) {
            int rowl = m_w + mt * 16 + rh * 8 + (lane >> 2);
            if (rowl < valid) {
                size_t base = (size_t)(off + mB + rowl) * FF + nf0;
#pragma unroll
                for (int nt = 0; nt < 4; nt++) {
                    float h0 = acc1[mt][nt][rh * 2 + 0];
                    float h1 = acc1[mt][nt][rh * 2 + 1];
                    float a0 = h0 * (1.f / (1.f + __expf(-h0))) * acc2[mt][nt][rh * 2 + 0];
                    float a1 = h1 * (1.f / (1.f + __expf(-h1))) * acc2[mt][nt][rh * 2 + 1];
                    __nv_bfloat162 hh, ll;
                    hh.x = __float2bfloat16(a0); ll.x = __float2bfloat16(a0 - __bfloat162float(hh.x));
                    hh.y = __float2bfloat16(a1); ll.y = __float2bfloat16(a1 - __bfloat162float(hh.y));
                    size_t gi = (base + n_w + nt * 8 + (lane & 3) * 2) >> 1;
                    outHi[gi] = *(u32*)&hh;
                    outLo[gi] = *(u32*)&ll;
                }
            }
        }
}

// ================= GEMM2: block 128x256, warp tile 64x64 single, bf16x3 =======
// stage: Ahi(128r) Alo(128r) w2h(256r) w2l(256r) = 2*10240 + 2*20480 = 61440
#define G2_STAGE (2 * TILE128 + 2 * TILE256)
#define G2_SMEM  (1024 + 3 * G2_STAGE)     // 185344

__global__ void __launch_bounds__(256, 1)
gemm2_mma(float* __restrict__ out) {
    extern __shared__ char smem[];
    const int e   = blockIdx.z;
    const int cnt = g_count[e];
    const int off = g_offset[e];
    const int mB  = blockIdx.y * 128;
    if (mB >= cnt) return;
    const int valid = min(128, cnt - mB);
    const int nd0   = blockIdx.x * 256;
    const int tid   = threadIdx.x;
    const int wid   = tid >> 5, lane = tid & 31;

    const u32 sb = smem_u32(smem);
    const size_t wbase = (size_t)e * DD * FF + (size_t)nd0 * FF;

    const int lrow = tid >> 2, lch = tid & 3;    // lrow 0..63
    const int arow0 = off + mB + min(lrow, valid - 1);
    const int arow1 = off + mB + min(lrow + 64, valid - 1);

    auto load_stage = [&](int s, int k0) {
        u32 st = sb + 1024 + s * G2_STAGE;
        const u32 co = (u32)(lrow * ROWB + lch * 16);
        const size_t ko = (size_t)(k0 + lch * 8);
        const size_t aa = (size_t)arow0 * FF + ko;
        const size_t ab = (size_t)arow1 * FF + ko;
        cp16(st + co,                      &g_acthi[aa]);
        cp16(st + co + 64 * ROWB,          &g_acthi[ab]);
        cp16(st + TILE128 + co,            &g_actlo[aa]);
        cp16(st + TILE128 + co + 64 * ROWB,&g_actlo[ab]);
        // B: 256 rows (4 groups) x hi/lo
        const u32 bb = st + 2 * TILE128;
#pragma unroll
        for (int g = 0; g < 4; g++) {
            const size_t go = wbase + (size_t)(lrow + g * 64) * FF + ko;
            cp16(bb + co + g * 64 * ROWB,           &g_w2hi[go]);
            cp16(bb + TILE256 + co + g * 64 * ROWB, &g_w2lo[go]);
        }
    };

    // warps: 2m x 4n, warp tile 64x64
    const int m_w = (wid >> 2) * 64, n_w = (wid & 3) * 64;
    const int lmat = lane >> 3, lr = lane & 7;
    const int aRow = m_w + (lmat & 1) * 8 + lr;
    const int aCol = (lmat >> 1) * 8;
    const int bRow = n_w + (lmat >> 1) * 8 + lr;
    const int bCol = (lmat & 1) * 8;

    float acc[4][8][4];
#pragma unroll
    for (int mt = 0; mt < 4; mt++)
#pragma unroll
        for (int nt = 0; nt < 8; nt++)
#pragma unroll
            for (int q = 0; q < 4; q++) acc[mt][nt][q] = 0.f;

    load_stage(0, 0);  cp_commit();
    load_stage(1, KT); cp_commit();

    const int NK = FF / KT;   // 128
    for (int kt = 0; kt < NK; kt++) {
        cp_wait1();
        __syncthreads();
        if (kt + 2 < NK) load_stage((kt + 2) % 3, (kt + 2) * KT);
        cp_commit();
        const u32 st = sb + 1024 + (kt % 3) * G2_STAGE;
        const u32 bb = st + 2 * TILE128;
#pragma unroll
        for (int k16 = 0; k16 < KT; k16 += 16) {
            u32 aH[4][4], aL[4][4];
#pragma unroll
            for (int mt = 0; mt < 4; mt++) {
                u32 ao = (u32)((aRow + mt * 16) * PITCH + k16 + aCol) * 2;
                ldsm4(st + ao, aH[mt]);
                ldsm4(st + TILE128 + ao, aL[mt]);
            }
            // NOTE: mt covers 64 rows within warp's 64-row tile: aRow+mt*16 <= m_w+63 ✓
#pragma unroll
            for (int p = 0; p < 4; p++) {
                u32 bo = (u32)((bRow + p * 16) * PITCH + k16 + bCol) * 2;
                u32 bh[4], bl[4];
                ldsm4(bb + bo,           bh);
                ldsm4(bb + TILE256 + bo, bl);
                // term-major ordering
#pragma unroll
                for (int mt = 0; mt < 4; mt++)
#pragma unroll
                    for (int q = 0; q < 2; q++)
                        mma16816(acc[mt][p * 2 + q], aH[mt], &bh[q * 2]);
#pragma unroll
                for (int mt = 0; mt < 4; mt++)
#pragma unroll
                    for (int q = 0; q < 2; q++)
                        mma16816(acc[mt][p * 2 + q], aH[mt], &bl[q * 2]);
#pragma unroll
                for (int mt = 0; mt < 4; mt++)
#pragma unroll
                    for (int q = 0; q < 2; q++)
                        mma16816(acc[mt][p * 2 + q], aL[mt], &bh[q * 2]);
            }
        }
        __syncthreads();
    }

    // epilogue: weighted atomic combine
#pragma unroll
    for (int mt = 0; mt < 4; mt++)
#pragma unroll
        for (int rh = 0; rh < 2; rh++) {
            int rowl = m_w + mt * 16 + rh * 8 + (lane >> 2);
            if (rowl < valid) {
                int gr = off + mB + rowl;
                int tok = g_rowTok[gr];
                float w = g_rowW[gr];
                float* op = &out[(size_t)tok * DD + nd0];
#pragma unroll
                for (int nt = 0; nt < 8; nt++) {
                    int c = n_w + nt * 8 + (lane & 3) * 2;
                    atomicAdd(op + c,     w * acc[mt][nt][rh * 2 + 0]);
                    atomicAdd(op + c + 1, w * acc[mt][nt][rh * 2 + 1]);
                }
            }
        }
}

// ================= host =================
extern "C" void kernel_launch(void* const* d_in, const int* in_sizes, int n_in,
                              void* d_out, int out_size) {
    const float* x  = (const float*)d_in[0];
    const float* gw = (const float*)d_in[1];
    const float* gb = (const float*)d_in[2];
    const float* w1 = (const float*)d_in[3];
    const float* w3 = (const float*)d_in[4];
    const float* w2 = (const float*)d_in[5];
    float* out = (float*)d_out;

    cudaFuncSetAttribute(gemm1_mma, cudaFuncAttributeMaxDynamicSharedMemorySize, G1_SMEM);
    cudaFuncSetAttribute(gemm2_mma, cudaFuncAttributeMaxDynamicSharedMemorySize, G2_SMEM);

    cudaMemsetAsync(out, 0, (size_t)out_size * sizeof(float), 0);

    const size_t totalChunks = (size_t)XC + 3 * (size_t)WC;
    split_all_kernel<<<(unsigned)((totalChunks + 255) / 256), 256>>>(x, w1, w3, w2);

    router_kernel<<<TT, 128>>>(x, gw, gb);
    scanscatter_kernel<<<1, 256>>>();

    dim3 g1(FF / 64, 16, EE);       // block 256 rows x 64 cols
    gemm1_mma<<<g1, 256, G1_SMEM>>>();
    dim3 g2(DD / 256, 32, EE);      // block 128 rows x 256 cols
    gemm2_mma<<<g2, 256, G2_SMEM>>>(out);
}

// round 6
// speedup vs baseline: 1.1448x; 1.1448x over previous
#include <cuda_runtime.h>
#include <cuda_bf16.h>

#define TT 4096
#define DD 1024
#define FF 4096
#define EE 8
#define NROWS (TT * 2)
#define NW   (EE * FF * DD)

typedef unsigned int u32;

// ================= device scratch (static) =================
__device__ __nv_bfloat16 g_xhi[TT * DD], g_xlo[TT * DD];
__device__ __nv_bfloat16 g_w1hi[NW], g_w1lo[NW];
__device__ __nv_bfloat16 g_w3hi[NW], g_w3lo[NW];
__device__ __nv_bfloat16 g_w2hi[NW], g_w2lo[NW];
__device__ __nv_bfloat16 g_acthi[(size_t)NROWS * FF], g_actlo[(size_t)NROWS * FF];

__device__ int   g_tokExp[TT * 2];
__device__ float g_tokW[TT * 2];
__device__ int   g_count[EE];
__device__ int   g_offset[EE];
__device__ int   g_cursor[EE];
__device__ int   g_rowTok[NROWS];
__device__ float g_rowW[NROWS];

// ================= PTX helpers (sm_80-generic only) =================
__device__ __forceinline__ u32 smem_u32(const void* p) {
    u32 a;
    asm("{ .reg .u64 t; cvta.to.shared.u64 t, %1; cvt.u32.u64 %0, t; }" : "=r"(a) : "l"(p));
    return a;
}
__device__ __forceinline__ void cp16(u32 dst, const void* src) {
    asm volatile("cp.async.cg.shared.global [%0], [%1], 16;" :: "r"(dst), "l"(src));
}
__device__ __forceinline__ void cp_commit() {
    asm volatile("cp.async.commit_group;" ::: "memory");
}
__device__ __forceinline__ void cp_wait1() {
    asm volatile("cp.async.wait_group 1;" ::: "memory");
}
__device__ __forceinline__ void ldsm4(u32 addr, u32* r) {
    asm volatile("ldmatrix.sync.aligned.m8n8.x4.shared.b16 {%0,%1,%2,%3}, [%4];"
        : "=r"(r[0]), "=r"(r[1]), "=r"(r[2]), "=r"(r[3]) : "r"(addr));
}
__device__ __forceinline__ void mma16816(float* d, const u32* a, const u32* b) {
    asm volatile(
        "mma.sync.aligned.m16n8k16.row.col.f32.bf16.bf16.f32 "
        "{%0,%1,%2,%3}, {%4,%5,%6,%7}, {%8,%9}, {%0,%1,%2,%3};"
        : "+f"(d[0]), "+f"(d[1]), "+f"(d[2]), "+f"(d[3])
        : "r"(a[0]), "r"(a[1]), "r"(a[2]), "r"(a[3]), "r"(b[0]), "r"(b[1]));
}

#define KT     32
#define PITCH  40                     // bf16 elems per smem row (80B: conflict-free)
#define ROWB   (PITCH * 2)            // 80 bytes per row
#define TILE128 (128 * ROWB)          // 10240 B
#define TILE64  (64 * ROWB)           // 5120 B

// ================= fused split (+reset) =================
#define XC  (TT * DD / 4)
#define WC  (NW / 4)
__global__ void __launch_bounds__(256)
split_all_kernel(const float* __restrict__ x,  const float* __restrict__ w1,
                 const float* __restrict__ w3, const float* __restrict__ w2) {
    if (blockIdx.x == 0 && threadIdx.x < EE) g_count[threadIdx.x] = 0;
    size_t i = (size_t)blockIdx.x * 256 + threadIdx.x;
    const float* src;
    __nv_bfloat16 *hi, *lo;
    if (i < XC)               { src = x;  hi = g_xhi;  lo = g_xlo; }
    else if (i < XC + WC)     { src = w1; hi = g_w1hi; lo = g_w1lo; i -= XC; }
    else if (i < XC + 2 * WC) { src = w3; hi = g_w3hi; lo = g_w3lo; i -= XC + WC; }
    else if (i < XC + 3 * WC) { src = w2; hi = g_w2hi; lo = g_w2lo; i -= XC + 2 * WC; }
    else return;
    float4 v = ((const float4*)src)[i];
    __nv_bfloat162 h01, h23, l01, l23;
    h01.x = __float2bfloat16(v.x); l01.x = __float2bfloat16(v.x - __bfloat162float(h01.x));
    h01.y = __float2bfloat16(v.y); l01.y = __float2bfloat16(v.y - __bfloat162float(h01.y));
    h23.x = __float2bfloat16(v.z); l23.x = __float2bfloat16(v.z - __bfloat162float(h23.x));
    h23.y = __float2bfloat16(v.w); l23.y = __float2bfloat16(v.w - __bfloat162float(h23.y));
    ((uint2*)hi)[i] = make_uint2(*(u32*)&h01, *(u32*)&h23);
    ((uint2*)lo)[i] = make_uint2(*(u32*)&l01, *(u32*)&l23);
}

// ================= router =================
__global__ void router_kernel(const float* __restrict__ x,
                              const float* __restrict__ gw,
                              const float* __restrict__ gb) {
    const int t = blockIdx.x, tid = threadIdx.x;
    float acc[EE];
#pragma unroll
    for (int e = 0; e < EE; e++) acc[e] = 0.f;
    const float* xr = x + (size_t)t * DD;
    for (int d = tid; d < DD; d += 128) {
        float xv = xr[d];
#pragma unroll
        for (int e = 0; e < EE; e++) acc[e] += xv * gw[e * DD + d];
    }
    __shared__ float red[EE][128];
#pragma unroll
    for (int e = 0; e < EE; e++) red[e][tid] = acc[e];
    __syncthreads();
    for (int s = 64; s > 0; s >>= 1) {
        if (tid < s) {
#pragma unroll
            for (int e = 0; e < EE; e++) red[e][tid] += red[e][tid + s];
        }
        __syncthreads();
    }
    if (tid == 0) {
        float lg[EE]; float mx = -1e30f;
#pragma unroll
        for (int e = 0; e < EE; e++) { lg[e] = red[e][0] + gb[e]; mx = fmaxf(mx, lg[e]); }
#pragma unroll
        for (int e = 0; e < EE; e++) lg[e] = expf(lg[e] - mx);
        int i1 = 0;
#pragma unroll
        for (int e = 1; e < EE; e++) if (lg[e] > lg[i1]) i1 = e;
        int i2 = (i1 == 0) ? 1 : 0;
#pragma unroll
        for (int e = 0; e < EE; e++) if (e != i2 && e != i1 && lg[e] > lg[i2]) i2 = e;
        float p1 = lg[i1], p2 = lg[i2], inv = 1.f / (p1 + p2);
        g_tokExp[t * 2 + 0] = i1; g_tokW[t * 2 + 0] = p1 * inv;
        g_tokExp[t * 2 + 1] = i2; g_tokW[t * 2 + 1] = p2 * inv;
        atomicAdd(&g_count[i1], 1);
        atomicAdd(&g_count[i2], 1);
    }
}

// ================= fused scan + scatter (single block) =================
__global__ void scanscatter_kernel() {
    const int tid = threadIdx.x;
    if (tid == 0) {
        int off = 0;
#pragma unroll
        for (int e = 0; e < EE; e++) { g_offset[e] = off; g_cursor[e] = off; off += g_count[e]; }
    }
    __syncthreads();
    for (int t = tid; t < TT; t += 256) {
#pragma unroll
        for (int s = 0; s < 2; s++) {
            int e = g_tokExp[t * 2 + s];
            int p = atomicAdd(&g_cursor[e], 1);
            g_rowTok[p] = t;
            g_rowW[p]   = g_tokW[t * 2 + s];
        }
    }
}

// ================= GEMM1: block 128x64, warp 32x32 dual-acc, 2 CTA/SM =========
// stage: Ahi/Alo (128r each) + w1h/w1l/w3h/w3l (64r each) = 2*10240 + 4*5120 = 40960
#define G1_STAGE (2 * TILE128 + 4 * TILE64)
#define G1_SMEM  (1024 + 2 * G1_STAGE)     // 82944

__global__ void __launch_bounds__(256, 2)
gemm1_mma() {
    extern __shared__ char smem[];
    const int e   = blockIdx.z;
    const int cnt = g_count[e];
    const int off = g_offset[e];
    const int mB  = blockIdx.y * 128;
    if (mB >= cnt) return;
    const int valid = min(128, cnt - mB);
    const int nf0   = blockIdx.x * 64;
    const int tid   = threadIdx.x;
    const int wid   = tid >> 5, lane = tid & 31;

    int* tokSm = (int*)smem;
    if (tid < 128) tokSm[tid] = g_rowTok[off + mB + min(tid, valid - 1)];
    __syncthreads();

    const u32 sb = smem_u32(smem);
    const size_t wbase = (size_t)e * FF * DD + (size_t)nf0 * DD;

    const int lrow = tid >> 2, lch = tid & 3;    // lrow 0..63
    const int tok0 = tokSm[lrow], tok1 = tokSm[lrow + 64];

    auto load_stage = [&](int s, int k0) {
        u32 st = sb + 1024 + s * G1_STAGE;
        const u32 co = (u32)(lrow * ROWB + lch * 16);
        const size_t ko = (size_t)(k0 + lch * 8);
        cp16(st + co,                       &g_xhi[(size_t)tok0 * DD + ko]);
        cp16(st + co + 64 * ROWB,           &g_xhi[(size_t)tok1 * DD + ko]);
        cp16(st + TILE128 + co,             &g_xlo[(size_t)tok0 * DD + ko]);
        cp16(st + TILE128 + co + 64 * ROWB, &g_xlo[(size_t)tok1 * DD + ko]);
        const size_t go = wbase + (size_t)lrow * DD + ko;
        const u32 bb = st + 2 * TILE128;
        cp16(bb + co,               &g_w1hi[go]);
        cp16(bb + TILE64 + co,      &g_w1lo[go]);
        cp16(bb + 2 * TILE64 + co,  &g_w3hi[go]);
        cp16(bb + 3 * TILE64 + co,  &g_w3lo[go]);
    };

    // warps: 4m x 2n, warp tile 32x32
    const int m_w = (wid >> 1) * 32, n_w = (wid & 1) * 32;
    const int lmat = lane >> 3, lr = lane & 7;
    const int aRow = m_w + (lmat & 1) * 8 + lr;
    const int aCol = (lmat >> 1) * 8;
    const int bRow = n_w + (lmat >> 1) * 8 + lr;
    const int bCol = (lmat & 1) * 8;

    float acc1[2][4][4], acc2[2][4][4];
#pragma unroll
    for (int mt = 0; mt < 2; mt++)
#pragma unroll
        for (int nt = 0; nt < 4; nt++)
#pragma unroll
            for (int q = 0; q < 4; q++) { acc1[mt][nt][q] = 0.f; acc2[mt][nt][q] = 0.f; }

    load_stage(0, 0);  cp_commit();
    load_stage(1, KT); cp_commit();

    const int NK = DD / KT;   // 32
    for (int kt = 0; kt < NK; kt++) {
        const int s = kt & 1;
        cp_wait1();
        __syncthreads();
        const u32 st = sb + 1024 + s * G1_STAGE;
        const u32 bb = st + 2 * TILE128;
#pragma unroll
        for (int k16 = 0; k16 < KT; k16 += 16) {
            u32 aH[2][4], aL[2][4];
#pragma unroll
            for (int mt = 0; mt < 2; mt++) {
                u32 ao = (u32)((aRow + mt * 16) * PITCH + k16 + aCol) * 2;
                ldsm4(st + ao, aH[mt]);
                ldsm4(st + TILE128 + ao, aL[mt]);
            }
#pragma unroll
            for (int p = 0; p < 2; p++) {
                u32 bo = (u32)((bRow + p * 16) * PITCH + k16 + bCol) * 2;
                u32 b1h[4], b1l[4], b3h[4], b3l[4];
                ldsm4(bb + bo,              b1h);
                ldsm4(bb + TILE64 + bo,     b1l);
                ldsm4(bb + 2 * TILE64 + bo, b3h);
                ldsm4(bb + 3 * TILE64 + bo, b3l);
#pragma unroll
                for (int mt = 0; mt < 2; mt++)
#pragma unroll
                    for (int q = 0; q < 2; q++) {
                        mma16816(acc1[mt][p * 2 + q], aH[mt], &b1h[q * 2]);
                        mma16816(acc2[mt][p * 2 + q], aH[mt], &b3h[q * 2]);
                    }
#pragma unroll
                for (int mt = 0; mt < 2; mt++)
#pragma unroll
                    for (int q = 0; q < 2; q++) {
                        mma16816(acc1[mt][p * 2 + q], aH[mt], &b1l[q * 2]);
                        mma16816(acc2[mt][p * 2 + q], aH[mt], &b3l[q * 2]);
                    }
#pragma unroll
                for (int mt = 0; mt < 2; mt++)
#pragma unroll
                    for (int q = 0; q < 2; q++) {
                        mma16816(acc1[mt][p * 2 + q], aL[mt], &b1h[q * 2]);
                        mma16816(acc2[mt][p * 2 + q], aL[mt], &b3h[q * 2]);
                    }
            }
        }
        __syncthreads();
        if (kt + 2 < NK) load_stage(s, (kt + 2) * KT);
        cp_commit();
    }

    // epilogue: silu(h1)*h3 -> bf16 hi/lo -> global
    u32* outHi = (u32*)g_acthi;
    u32* outLo = (u32*)g_actlo;
#pragma unroll
    for (int mt = 0; mt < 2; mt++)
#pragma unroll
        for (int rh = 0; rh < 2; rh++) {
            int rowl = m_w + mt * 16 + rh * 8 + (lane >> 2);
            if (rowl < valid) {
                size_t base = (size_t)(off + mB + rowl) * FF + nf0;
#pragma unroll
                for (int nt = 0; nt < 4; nt++) {
                    float h0 = acc1[mt][nt][rh * 2 + 0];
                    float h1 = acc1[mt][nt][rh * 2 + 1];
                    float a0 = h0 * (1.f / (1.f + __expf(-h0))) * acc2[mt][nt][rh * 2 + 0];
                    float a1 = h1 * (1.f / (1.f + __expf(-h1))) * acc2[mt][nt][rh * 2 + 1];
                    __nv_bfloat162 hh, ll;
                    hh.x = __float2bfloat16(a0); ll.x = __float2bfloat16(a0 - __bfloat162float(hh.x));
                    hh.y = __float2bfloat16(a1); ll.y = __float2bfloat16(a1 - __bfloat162float(hh.y));
                    size_t gi = (base + n_w + nt * 8 + (lane & 3) * 2) >> 1;
                    outHi[gi] = *(u32*)&hh;
                    outLo[gi] = *(u32*)&ll;
                }
            }
        }
}

// ================= GEMM2: block 128x128, warp 32x64, 2 CTA/SM =================
// stage: Ahi/Alo (128r) + w2h/w2l (128r) = 4*10240 = 40960
#define G2_STAGE (4 * TILE128)
#define G2_SMEM  (1024 + 2 * G2_STAGE)     // 82944

__global__ void __launch_bounds__(256, 2)
gemm2_mma(float* __restrict__ out) {
    extern __shared__ char smem[];
    const int e   = blockIdx.z;
    const int cnt = g_count[e];
    const int off = g_offset[e];
    const int mB  = blockIdx.y * 128;
    if (mB >= cnt) return;
    const int valid = min(128, cnt - mB);
    const int nd0   = blockIdx.x * 128;
    const int tid   = threadIdx.x;
    const int wid   = tid >> 5, lane = tid & 31;

    const u32 sb = smem_u32(smem);
    const size_t wbase = (size_t)e * DD * FF + (size_t)nd0 * FF;

    const int lrow = tid >> 2, lch = tid & 3;    // lrow 0..63
    const int arow0 = off + mB + min(lrow, valid - 1);
    const int arow1 = off + mB + min(lrow + 64, valid - 1);

    auto load_stage = [&](int s, int k0) {
        u32 st = sb + 1024 + s * G2_STAGE;
        const u32 co = (u32)(lrow * ROWB + lch * 16);
        const size_t ko = (size_t)(k0 + lch * 8);
        const size_t aa = (size_t)arow0 * FF + ko;
        const size_t ab = (size_t)arow1 * FF + ko;
        cp16(st + co,                       &g_acthi[aa]);
        cp16(st + co + 64 * ROWB,           &g_acthi[ab]);
        cp16(st + TILE128 + co,             &g_actlo[aa]);
        cp16(st + TILE128 + co + 64 * ROWB, &g_actlo[ab]);
        const u32 bb = st + 2 * TILE128;
        const size_t g0 = wbase + (size_t)lrow * FF + ko;
        const size_t g1 = wbase + (size_t)(lrow + 64) * FF + ko;
        cp16(bb + co,                       &g_w2hi[g0]);
        cp16(bb + co + 64 * ROWB,           &g_w2hi[g1]);
        cp16(bb + TILE128 + co,             &g_w2lo[g0]);
        cp16(bb + TILE128 + co + 64 * ROWB, &g_w2lo[g1]);
    };

    // warps: 4m x 2n, warp tile 32x64
    const int m_w = (wid >> 1) * 32, n_w = (wid & 1) * 64;
    const int lmat = lane >> 3, lr = lane & 7;
    const int aRow = m_w + (lmat & 1) * 8 + lr;
    const int aCol = (lmat >> 1) * 8;
    const int bRow = n_w + (lmat >> 1) * 8 + lr;
    const int bCol = (lmat & 1) * 8;

    float acc[2][8][4];
#pragma unroll
    for (int mt = 0; mt < 2; mt++)
#pragma unroll
        for (int nt = 0; nt < 8; nt++)
#pragma unroll
            for (int q = 0; q < 4; q++) acc[mt][nt][q] = 0.f;

    load_stage(0, 0);  cp_commit();
    load_stage(1, KT); cp_commit();

    const int NK = FF / KT;   // 128
    for (int kt = 0; kt < NK; kt++) {
        const int s = kt & 1;
        cp_wait1();
        __syncthreads();
        const u32 st = sb + 1024 + s * G2_STAGE;
        const u32 bb = st + 2 * TILE128;
#pragma unroll
        for (int k16 = 0; k16 < KT; k16 += 16) {
            u32 aH[2][4], aL[2][4];
#pragma unroll
            for (int mt = 0; mt < 2; mt++) {
                u32 ao = (u32)((aRow + mt * 16) * PITCH + k16 + aCol) * 2;
                ldsm4(st + ao, aH[mt]);
                ldsm4(st + TILE128 + ao, aL[mt]);
            }
#pragma unroll
            for (int p = 0; p < 4; p++) {
                u32 bo = (u32)((bRow + p * 16) * PITCH + k16 + bCol) * 2;
                u32 bh[4], bl[4];
                ldsm4(bb + bo,           bh);
                ldsm4(bb + TILE128 + bo, bl);
#pragma unroll
                for (int mt = 0; mt < 2; mt++)
#pragma unroll
                    for (int q = 0; q < 2; q++)
                        mma16816(acc[mt][p * 2 + q], aH[mt], &bh[q * 2]);
#pragma unroll
                for (int mt = 0; mt < 2; mt++)
#pragma unroll
                    for (int q = 0; q < 2; q++)
                        mma16816(acc[mt][p * 2 + q], aH[mt], &bl[q * 2]);
#pragma unroll
                for (int mt = 0; mt < 2; mt++)
#pragma unroll
                    for (int q = 0; q < 2; q++)
                        mma16816(acc[mt][p * 2 + q], aL[mt], &bh[q * 2]);
            }
        }
        __syncthreads();
        if (kt + 2 < NK) load_stage(s, (kt + 2) * KT);
        cp_commit();
    }

    // epilogue: weighted atomic combine
#pragma unroll
    for (int mt = 0; mt < 2; mt++)
#pragma unroll
        for (int rh = 0; rh < 2; rh++) {
            int rowl = m_w + mt * 16 + rh * 8 + (lane >> 2);
            if (rowl < valid) {
                int gr = off + mB + rowl;
                int tok = g_rowTok[gr];
                float w = g_rowW[gr];
                float* op = &out[(size_t)tok * DD + nd0];
#pragma unroll
                for (int nt = 0; nt < 8; nt++) {
                    int c = n_w + nt * 8 + (lane & 3) * 2;
                    atomicAdd(op + c,     w * acc[mt][nt][rh * 2 + 0]);
                    atomicAdd(op + c + 1, w * acc[mt][nt][rh * 2 + 1]);
                }
            }
        }
}

// ================= host =================
extern "C" void kernel_launch(void* const* d_in, const int* in_sizes, int n_in,
                              void* d_out, int out_size) {
    const float* x  = (const float*)d_in[0];
    const float* gw = (const float*)d_in[1];
    const float* gb = (const float*)d_in[2];
    const float* w1 = (const float*)d_in[3];
    const float* w3 = (const float*)d_in[4];
    const float* w2 = (const float*)d_in[5];
    float* out = (float*)d_out;

    cudaFuncSetAttribute(gemm1_mma, cudaFuncAttributeMaxDynamicSharedMemorySize, G1_SMEM);
    cudaFuncSetAttribute(gemm2_mma, cudaFuncAttributeMaxDynamicSharedMemorySize, G2_SMEM);

    cudaMemsetAsync(out, 0, (size_t)out_size * sizeof(float), 0);

    const size_t totalChunks = (size_t)XC + 3 * (size_t)WC;
    split_all_kernel<<<(unsigned)((totalChunks + 255) / 256), 256>>>(x, w1, w3, w2);

    router_kernel<<<TT, 128>>>(x, gw, gb);
    scanscatter_kernel<<<1, 256>>>();

    dim3 g1(FF / 64, 32, EE);        // block 128 rows x 64 cols
    gemm1_mma<<<g1, 256, G1_SMEM>>>();
    dim3 g2(DD / 128, 32, EE);       // block 128 rows x 128 cols
    gemm2_mma<<<g2, 256, G2_SMEM>>>(out);
}

// round 7
// speedup vs baseline: 1.5583x; 1.3612x over previous
#include <cuda_runtime.h>
#include <cuda_fp16.h>

#define TT 4096
#define DD 1024
#define FF 4096
#define EE 8
#define NROWS (TT * 2)
#define NW   (EE * FF * DD)

typedef unsigned int u32;

// ================= device scratch (static) =================
__device__ __half g_xhi[TT * DD], g_xlo[TT * DD];
__device__ __half g_w1h[NW];
__device__ __half g_w3h[NW];
__device__ __half g_w2h[NW];
__device__ __half g_acthi[(size_t)NROWS * FF], g_actlo[(size_t)NROWS * FF];

__device__ int   g_tokExp[TT * 2];
__device__ float g_tokW[TT * 2];
__device__ int   g_count[EE];
__device__ int   g_offset[EE];
__device__ int   g_cursor[EE];
__device__ int   g_rowTok[NROWS];
__device__ float g_rowW[NROWS];

// ================= PTX helpers (sm_80-generic only) =================
__device__ __forceinline__ u32 smem_u32(const void* p) {
    u32 a;
    asm("{ .reg .u64 t; cvta.to.shared.u64 t, %1; cvt.u32.u64 %0, t; }" : "=r"(a) : "l"(p));
    return a;
}
__device__ __forceinline__ void cp16(u32 dst, const void* src) {
    asm volatile("cp.async.cg.shared.global [%0], [%1], 16;" :: "r"(dst), "l"(src));
}
__device__ __forceinline__ void cp_commit() {
    asm volatile("cp.async.commit_group;" ::: "memory");
}
__device__ __forceinline__ void cp_wait1() {
    asm volatile("cp.async.wait_group 1;" ::: "memory");
}
__device__ __forceinline__ void ldsm4(u32 addr, u32* r) {
    asm volatile("ldmatrix.sync.aligned.m8n8.x4.shared.b16 {%0,%1,%2,%3}, [%4];"
        : "=r"(r[0]), "=r"(r[1]), "=r"(r[2]), "=r"(r[3]) : "r"(addr));
}
__device__ __forceinline__ void mma16816(float* d, const u32* a, const u32* b) {
    asm volatile(
        "mma.sync.aligned.m16n8k16.row.col.f32.f16.f16.f32 "
        "{%0,%1,%2,%3}, {%4,%5,%6,%7}, {%8,%9}, {%0,%1,%2,%3};"
        : "+f"(d[0]), "+f"(d[1]), "+f"(d[2]), "+f"(d[3])
        : "r"(a[0]), "r"(a[1]), "r"(a[2]), "r"(a[3]), "r"(b[0]), "r"(b[1]));
}

#define KT     32
#define PITCH  40                     // fp16 elems per smem row (80B: conflict-free)
#define ROWB   (PITCH * 2)            // 80 bytes per row
#define TILE128 (128 * ROWB)          // 10240 B
#define TILE64  (64 * ROWB)           // 5120 B

// ================= fused split (+reset) =================
// x -> exact fp16 hi/lo split; weights -> single fp16 (hi)
#define XC  (TT * DD / 4)
#define WC  (NW / 4)
__global__ void __launch_bounds__(256)
split_all_kernel(const float* __restrict__ x,  const float* __restrict__ w1,
                 const float* __restrict__ w3, const float* __restrict__ w2) {
    if (blockIdx.x == 0 && threadIdx.x < EE) g_count[threadIdx.x] = 0;
    size_t i = (size_t)blockIdx.x * 256 + threadIdx.x;
    if (i < XC) {
        float4 v = ((const float4*)x)[i];
        __half2 h01, h23, l01, l23;
        h01.x = __float2half(v.x); l01.x = __float2half(v.x - __half2float(h01.x));
        h01.y = __float2half(v.y); l01.y = __float2half(v.y - __half2float(h01.y));
        h23.x = __float2half(v.z); l23.x = __float2half(v.z - __half2float(h23.x));
        h23.y = __float2half(v.w); l23.y = __float2half(v.w - __half2float(h23.y));
        ((uint2*)g_xhi)[i] = make_uint2(*(u32*)&h01, *(u32*)&h23);
        ((uint2*)g_xlo)[i] = make_uint2(*(u32*)&l01, *(u32*)&l23);
        return;
    }
    const float* src;
    __half* hi;
    size_t j = i - XC;
    if (j < WC)          { src = w1; hi = g_w1h; }
    else if (j < 2 * WC) { src = w3; hi = g_w3h; j -= WC; }
    else if (j < 3 * WC) { src = w2; hi = g_w2h; j -= 2 * WC; }
    else return;
    float4 v = ((const float4*)src)[j];
    __half2 h01, h23;
    h01.x = __float2half(v.x); h01.y = __float2half(v.y);
    h23.x = __float2half(v.z); h23.y = __float2half(v.w);
    ((uint2*)hi)[j] = make_uint2(*(u32*)&h01, *(u32*)&h23);
}

// ================= router =================
__global__ void router_kernel(const float* __restrict__ x,
                              const float* __restrict__ gw,
                              const float* __restrict__ gb) {
    const int t = blockIdx.x, tid = threadIdx.x;
    float acc[EE];
#pragma unroll
    for (int e = 0; e < EE; e++) acc[e] = 0.f;
    const float* xr = x + (size_t)t * DD;
    for (int d = tid; d < DD; d += 128) {
        float xv = xr[d];
#pragma unroll
        for (int e = 0; e < EE; e++) acc[e] += xv * gw[e * DD + d];
    }
    __shared__ float red[EE][128];
#pragma unroll
    for (int e = 0; e < EE; e++) red[e][tid] = acc[e];
    __syncthreads();
    for (int s = 64; s > 0; s >>= 1) {
        if (tid < s) {
#pragma unroll
            for (int e = 0; e < EE; e++) red[e][tid] += red[e][tid + s];
        }
        __syncthreads();
    }
    if (tid == 0) {
        float lg[EE]; float mx = -1e30f;
#pragma unroll
        for (int e = 0; e < EE; e++) { lg[e] = red[e][0] + gb[e]; mx = fmaxf(mx, lg[e]); }
#pragma unroll
        for (int e = 0; e < EE; e++) lg[e] = expf(lg[e] - mx);
        int i1 = 0;
#pragma unroll
        for (int e = 1; e < EE; e++) if (lg[e] > lg[i1]) i1 = e;
        int i2 = (i1 == 0) ? 1 : 0;
#pragma unroll
        for (int e = 0; e < EE; e++) if (e != i2 && e != i1 && lg[e] > lg[i2]) i2 = e;
        float p1 = lg[i1], p2 = lg[i2], inv = 1.f / (p1 + p2);
        g_tokExp[t * 2 + 0] = i1; g_tokW[t * 2 + 0] = p1 * inv;
        g_tokExp[t * 2 + 1] = i2; g_tokW[t * 2 + 1] = p2 * inv;
        atomicAdd(&g_count[i1], 1);
        atomicAdd(&g_count[i2], 1);
    }
}

// ================= fused scan + scatter (single block) =================
__global__ void scanscatter_kernel() {
    const int tid = threadIdx.x;
    if (tid == 0) {
        int off = 0;
#pragma unroll
        for (int e = 0; e < EE; e++) { g_offset[e] = off; g_cursor[e] = off; off += g_count[e]; }
    }
    __syncthreads();
    for (int t = tid; t < TT; t += 256) {
#pragma unroll
        for (int s = 0; s < 2; s++) {
            int e = g_tokExp[t * 2 + s];
            int p = atomicAdd(&g_cursor[e], 1);
            g_rowTok[p] = t;
            g_rowW[p]   = g_tokW[t * 2 + s];
        }
    }
}

// ================= GEMM1: block 128x64, fp16x2, 3-stage, 2 CTA/SM =============
// stage: Ahi(128r) + Alo(128r) + w1h(64r) + w3h(64r) = 2*10240 + 2*5120 = 30720
#define G1_STAGE (2 * TILE128 + 2 * TILE64)
#define G1_SMEM  (1024 + 3 * G1_STAGE)     // 93184

__global__ void __launch_bounds__(256, 2)
gemm1_mma() {
    extern __shared__ char smem[];
    const int e   = blockIdx.z;
    const int cnt = g_count[e];
    const int off = g_offset[e];
    const int mB  = blockIdx.y * 128;
    if (mB >= cnt) return;
    const int valid = min(128, cnt - mB);
    const int nf0   = blockIdx.x * 64;
    const int tid   = threadIdx.x;
    const int wid   = tid >> 5, lane = tid & 31;

    int* tokSm = (int*)smem;
    if (tid < 128) tokSm[tid] = g_rowTok[off + mB + min(tid, valid - 1)];
    __syncthreads();

    const u32 sb = smem_u32(smem);
    const size_t wbase = (size_t)e * FF * DD + (size_t)nf0 * DD;

    const int lrow = tid >> 2, lch = tid & 3;    // lrow 0..63
    const int tok0 = tokSm[lrow], tok1 = tokSm[lrow + 64];

    auto load_stage = [&](int s, int k0) {
        u32 st = sb + 1024 + s * G1_STAGE;
        const u32 co = (u32)(lrow * ROWB + lch * 16);
        const size_t ko = (size_t)(k0 + lch * 8);
        cp16(st + co,                       &g_xhi[(size_t)tok0 * DD + ko]);
        cp16(st + co + 64 * ROWB,           &g_xhi[(size_t)tok1 * DD + ko]);
        cp16(st + TILE128 + co,             &g_xlo[(size_t)tok0 * DD + ko]);
        cp16(st + TILE128 + co + 64 * ROWB, &g_xlo[(size_t)tok1 * DD + ko]);
        const size_t go = wbase + (size_t)lrow * DD + ko;
        const u32 bb = st + 2 * TILE128;
        cp16(bb + co,          &g_w1h[go]);
        cp16(bb + TILE64 + co, &g_w3h[go]);
    };

    // warps: 4m x 2n, warp tile 32x32 (dual accumulators h1,h3)
    const int m_w = (wid >> 1) * 32, n_w = (wid & 1) * 32;
    const int lmat = lane >> 3, lr = lane & 7;
    const int aRow = m_w + (lmat & 1) * 8 + lr;
    const int aCol = (lmat >> 1) * 8;
    const int bRow = n_w + (lmat >> 1) * 8 + lr;
    const int bCol = (lmat & 1) * 8;

    float acc1[2][4][4], acc2[2][4][4];
#pragma unroll
    for (int mt = 0; mt < 2; mt++)
#pragma unroll
        for (int nt = 0; nt < 4; nt++)
#pragma unroll
            for (int q = 0; q < 4; q++) { acc1[mt][nt][q] = 0.f; acc2[mt][nt][q] = 0.f; }

    load_stage(0, 0);  cp_commit();
    load_stage(1, KT); cp_commit();

    const int NK = DD / KT;   // 32
    for (int kt = 0; kt < NK; kt++) {
        cp_wait1();
        __syncthreads();                                // single barrier per iter
        if (kt + 2 < NK) load_stage((kt + 2) % 3, (kt + 2) * KT);
        cp_commit();
        const u32 st = sb + 1024 + (kt % 3) * G1_STAGE;
        const u32 bb = st + 2 * TILE128;
#pragma unroll
        for (int k16 = 0; k16 < KT; k16 += 16) {
            u32 aH[2][4], aL[2][4];
#pragma unroll
            for (int mt = 0; mt < 2; mt++) {
                u32 ao = (u32)((aRow + mt * 16) * PITCH + k16 + aCol) * 2;
                ldsm4(st + ao, aH[mt]);
                ldsm4(st + TILE128 + ao, aL[mt]);
            }
#pragma unroll
            for (int p = 0; p < 2; p++) {
                u32 bo = (u32)((bRow + p * 16) * PITCH + k16 + bCol) * 2;
                u32 b1h[4], b3h[4];
                ldsm4(bb + bo,          b1h);
                ldsm4(bb + TILE64 + bo, b3h);
#pragma unroll
                for (int mt = 0; mt < 2; mt++)
#pragma unroll
                    for (int q = 0; q < 2; q++) {
                        mma16816(acc1[mt][p * 2 + q], aH[mt], &b1h[q * 2]);
                        mma16816(acc2[mt][p * 2 + q], aH[mt], &b3h[q * 2]);
                    }
#pragma unroll
                for (int mt = 0; mt < 2; mt++)
#pragma unroll
                    for (int q = 0; q < 2; q++) {
                        mma16816(acc1[mt][p * 2 + q], aL[mt], &b1h[q * 2]);
                        mma16816(acc2[mt][p * 2 + q], aL[mt], &b3h[q * 2]);
                    }
            }
        }
    }

    // epilogue: silu(h1)*h3 -> fp16 hi/lo -> global
    u32* outHi = (u32*)g_acthi;
    u32* outLo = (u32*)g_actlo;
#pragma unroll
    for (int mt = 0; mt < 2; mt++)
#pragma unroll
        for (int rh = 0; rh < 2; rh++) {
            int rowl = m_w + mt * 16 + rh * 8 + (lane >> 2);
            if (rowl < valid) {
                size_t base = (size_t)(off + mB + rowl) * FF + nf0;
#pragma unroll
                for (int nt = 0; nt < 4; nt++) {
                    float h0 = acc1[mt][nt][rh * 2 + 0];
                    float h1 = acc1[mt][nt][rh * 2 + 1];
                    float a0 = h0 * (1.f / (1.f + __expf(-h0))) * acc2[mt][nt][rh * 2 + 0];
                    float a1 = h1 * (1.f / (1.f + __expf(-h1))) * acc2[mt][nt][rh * 2 + 1];
                    __half2 hh, ll;
                    hh.x = __float2half(a0); ll.x = __float2half(a0 - __half2float(hh.x));
                    hh.y = __float2half(a1); ll.y = __float2half(a1 - __half2float(hh.y));
                    size_t gi = (base + n_w + nt * 8 + (lane & 3) * 2) >> 1;
                    outHi[gi] = *(u32*)&hh;
                    outLo[gi] = *(u32*)&ll;
                }
            }
        }
}

// ================= GEMM2: block 128x128, fp16x2, 3-stage, 2 CTA/SM ============
// stage: Ahi(128r) + Alo(128r) + w2h(128r) = 3*10240 = 30720
#define G2_STAGE (3 * TILE128)
#define G2_SMEM  (1024 + 3 * G2_STAGE)     // 93184

__global__ void __launch_bounds__(256, 2)
gemm2_mma(float* __restrict__ out) {
    extern __shared__ char smem[];
    const int e   = blockIdx.z;
    const int cnt = g_count[e];
    const int off = g_offset[e];
    const int mB  = blockIdx.y * 128;
    if (mB >= cnt) return;
    const int valid = min(128, cnt - mB);
    const int nd0   = blockIdx.x * 128;
    const int tid   = threadIdx.x;
    const int wid   = tid >> 5, lane = tid & 31;

    const u32 sb = smem_u32(smem);
    const size_t wbase = (size_t)e * DD * FF + (size_t)nd0 * FF;

    const int lrow = tid >> 2, lch = tid & 3;    // lrow 0..63
    const int arow0 = off + mB + min(lrow, valid - 1);
    const int arow1 = off + mB + min(lrow + 64, valid - 1);

    auto load_stage = [&](int s, int k0) {
        u32 st = sb + 1024 + s * G2_STAGE;
        const u32 co = (u32)(lrow * ROWB + lch * 16);
        const size_t ko = (size_t)(k0 + lch * 8);
        const size_t aa = (size_t)arow0 * FF + ko;
        const size_t ab = (size_t)arow1 * FF + ko;
        cp16(st + co,                       &g_acthi[aa]);
        cp16(st + co + 64 * ROWB,           &g_acthi[ab]);
        cp16(st + TILE128 + co,             &g_actlo[aa]);
        cp16(st + TILE128 + co + 64 * ROWB, &g_actlo[ab]);
        const u32 bb = st + 2 * TILE128;
        const size_t g0 = wbase + (size_t)lrow * FF + ko;
        const size_t g1 = wbase + (size_t)(lrow + 64) * FF + ko;
        cp16(bb + co,             &g_w2h[g0]);
        cp16(bb + co + 64 * ROWB, &g_w2h[g1]);
    };

    // warps: 4m x 2n, warp tile 32x64
    const int m_w = (wid >> 1) * 32, n_w = (wid & 1) * 64;
    const int lmat = lane >> 3, lr = lane & 7;
    const int aRow = m_w + (lmat & 1) * 8 + lr;
    const int aCol = (lmat >> 1) * 8;
    const int bRow = n_w + (lmat >> 1) * 8 + lr;
    const int bCol = (lmat & 1) * 8;

    float acc[2][8][4];
#pragma unroll
    for (int mt = 0; mt < 2; mt++)
#pragma unroll
        for (int nt = 0; nt < 8; nt++)
#pragma unroll
            for (int q = 0; q < 4; q++) acc[mt][nt][q] = 0.f;

    load_stage(0, 0);  cp_commit();
    load_stage(1, KT); cp_commit();

    const int NK = FF / KT;   // 128
    for (int kt = 0; kt < NK; kt++) {
        cp_wait1();
        __syncthreads();
        if (kt + 2 < NK) load_stage((kt + 2) % 3, (kt + 2) * KT);
        cp_commit();
        const u32 st = sb + 1024 + (kt % 3) * G2_STAGE;
        const u32 bb = st + 2 * TILE128;
#pragma unroll
        for (int k16 = 0; k16 < KT; k16 += 16) {
            u32 aH[2][4], aL[2][4];
#pragma unroll
            for (int mt = 0; mt < 2; mt++) {
                u32 ao = (u32)((aRow + mt * 16) * PITCH + k16 + aCol) * 2;
                ldsm4(st + ao, aH[mt]);
                ldsm4(st + TILE128 + ao, aL[mt]);
            }
#pragma unroll
            for (int p = 0; p < 4; p++) {
                u32 bo = (u32)((bRow + p * 16) * PITCH + k16 + bCol) * 2;
                u32 bh[4];
                ldsm4(bb + bo, bh);
#pragma unroll
                for (int mt = 0; mt < 2; mt++)
#pragma unroll
                    for (int q = 0; q < 2; q++)
                        mma16816(acc[mt][p * 2 + q], aH[mt], &bh[q * 2]);
#pragma unroll
                for (int mt = 0; mt < 2; mt++)
#pragma unroll
                    for (int q = 0; q < 2; q++)
                        mma16816(acc[mt][p * 2 + q], aL[mt], &bh[q * 2]);
            }
        }
    }

    // epilogue: weighted atomic combine
#pragma unroll
    for (int mt = 0; mt < 2; mt++)
#pragma unroll
        for (int rh = 0; rh < 2; rh++) {
            int rowl = m_w + mt * 16 + rh * 8 + (lane >> 2);
            if (rowl < valid) {
                int gr = off + mB + rowl;
                int tok = g_rowTok[gr];
                float w = g_rowW[gr];
                float* op = &out[(size_t)tok * DD + nd0];
#pragma unroll
                for (int nt = 0; nt < 8; nt++) {
                    int c = n_w + nt * 8 + (lane & 3) * 2;
                    atomicAdd(op + c,     w * acc[mt][nt][rh * 2 + 0]);
                    atomicAdd(op + c + 1, w * acc[mt][nt][rh * 2 + 1]);
                }
            }
        }
}

// ================= host =================
extern "C" void kernel_launch(void* const* d_in, const int* in_sizes, int n_in,
                              void* d_out, int out_size) {
    const float* x  = (const float*)d_in[0];
    const float* gw = (const float*)d_in[1];
    const float* gb = (const float*)d_in[2];
    const float* w1 = (const float*)d_in[3];
    const float* w3 = (const float*)d_in[4];
    const float* w2 = (const float*)d_in[5];
    float* out = (float*)d_out;

    cudaFuncSetAttribute(gemm1_mma, cudaFuncAttributeMaxDynamicSharedMemorySize, G1_SMEM);
    cudaFuncSetAttribute(gemm2_mma, cudaFuncAttributeMaxDynamicSharedMemorySize, G2_SMEM);

    cudaMemsetAsync(out, 0, (size_t)out_size * sizeof(float), 0);

    const size_t totalChunks = (size_t)XC + 3 * (size_t)WC;
    split_all_kernel<<<(unsigned)((totalChunks + 255) / 256), 256>>>(x, w1, w3, w2);

    router_kernel<<<TT, 128>>>(x, gw, gb);
    scanscatter_kernel<<<1, 256>>>();

    dim3 g1(FF / 64, 32, EE);        // block 128 rows x 64 cols
    gemm1_mma<<<g1, 256, G1_SMEM>>>();
    dim3 g2(DD / 128, 32, EE);       // block 128 rows x 128 cols
    gemm2_mma<<<g2, 256, G2_SMEM>>>(out);
}

// round 8
// speedup vs baseline: 2.5197x; 1.6170x over previous
#include <cuda_runtime.h>
#include <cuda_fp16.h>

#define TT 4096
#define DD 1024
#define FF 4096
#define EE 8
#define NROWS (TT * 2)
#define NW   (EE * FF * DD)

typedef unsigned int u32;

// ================= device scratch (static) =================
__device__ __half g_xh[TT * DD];
__device__ __half g_w1h[NW];
__device__ __half g_w3h[NW];
__device__ __half g_w2h[NW];
__device__ __half g_acth[(size_t)NROWS * FF];

__device__ int   g_tokExp[TT * 2];
__device__ float g_tokW[TT * 2];
__device__ int   g_count[EE];
__device__ int   g_offset[EE];
__device__ int   g_cursor[EE];
__device__ int   g_rowTok[NROWS];
__device__ float g_rowW[NROWS];

// ================= PTX helpers (sm_80-generic only) =================
__device__ __forceinline__ u32 smem_u32(const void* p) {
    u32 a;
    asm("{ .reg .u64 t; cvta.to.shared.u64 t, %1; cvt.u32.u64 %0, t; }" : "=r"(a) : "l"(p));
    return a;
}
__device__ __forceinline__ void cp16(u32 dst, const void* src) {
    asm volatile("cp.async.cg.shared.global [%0], [%1], 16;" :: "r"(dst), "l"(src));
}
__device__ __forceinline__ void cp_commit() {
    asm volatile("cp.async.commit_group;" ::: "memory");
}
__device__ __forceinline__ void cp_wait2() {
    asm volatile("cp.async.wait_group 2;" ::: "memory");
}
__device__ __forceinline__ void ldsm4(u32 addr, u32* r) {
    asm volatile("ldmatrix.sync.aligned.m8n8.x4.shared.b16 {%0,%1,%2,%3}, [%4];"
        : "=r"(r[0]), "=r"(r[1]), "=r"(r[2]), "=r"(r[3]) : "r"(addr));
}
__device__ __forceinline__ void mma16816(float* d, const u32* a, const u32* b) {
    asm volatile(
        "mma.sync.aligned.m16n8k16.row.col.f32.f16.f16.f32 "
        "{%0,%1,%2,%3}, {%4,%5,%6,%7}, {%8,%9}, {%0,%1,%2,%3};"
        : "+f"(d[0]), "+f"(d[1]), "+f"(d[2]), "+f"(d[3])
        : "r"(a[0]), "r"(a[1]), "r"(a[2]), "r"(a[3]), "r"(b[0]), "r"(b[1]));
}

#define KT     32
#define PITCH  40                     // fp16 elems per smem row (80B: conflict-free)
#define ROWB   (PITCH * 2)            // 80 bytes per row
#define TILE128 (128 * ROWB)          // 10240 B
#define TILE64  (64 * ROWB)           // 5120 B

// ================= fused convert (+reset): all tensors -> fp16 ================
#define XC  (TT * DD / 4)
#define WC  (NW / 4)
__global__ void __launch_bounds__(256)
split_all_kernel(const float* __restrict__ x,  const float* __restrict__ w1,
                 const float* __restrict__ w3, const float* __restrict__ w2) {
    if (blockIdx.x == 0 && threadIdx.x < EE) g_count[threadIdx.x] = 0;
    size_t i = (size_t)blockIdx.x * 256 + threadIdx.x;
    const float* src;
    __half* dst;
    if (i < XC)               { src = x;  dst = g_xh; }
    else if (i < XC + WC)     { src = w1; dst = g_w1h; i -= XC; }
    else if (i < XC + 2 * WC) { src = w3; dst = g_w3h; i -= XC + WC; }
    else if (i < XC + 3 * WC) { src = w2; dst = g_w2h; i -= XC + 2 * WC; }
    else return;
    float4 v = ((const float4*)src)[i];
    __half2 h01, h23;
    h01.x = __float2half(v.x); h01.y = __float2half(v.y);
    h23.x = __float2half(v.z); h23.y = __float2half(v.w);
    ((uint2*)dst)[i] = make_uint2(*(u32*)&h01, *(u32*)&h23);
}

// ================= router =================
__global__ void router_kernel(const float* __restrict__ x,
                              const float* __restrict__ gw,
                              const float* __restrict__ gb) {
    const int t = blockIdx.x, tid = threadIdx.x;
    float acc[EE];
#pragma unroll
    for (int e = 0; e < EE; e++) acc[e] = 0.f;
    const float* xr = x + (size_t)t * DD;
    for (int d = tid; d < DD; d += 128) {
        float xv = xr[d];
#pragma unroll
        for (int e = 0; e < EE; e++) acc[e] += xv * gw[e * DD + d];
    }
    __shared__ float red[EE][128];
#pragma unroll
    for (int e = 0; e < EE; e++) red[e][tid] = acc[e];
    __syncthreads();
    for (int s = 64; s > 0; s >>= 1) {
        if (tid < s) {
#pragma unroll
            for (int e = 0; e < EE; e++) red[e][tid] += red[e][tid + s];
        }
        __syncthreads();
    }
    if (tid == 0) {
        float lg[EE]; float mx = -1e30f;
#pragma unroll
        for (int e = 0; e < EE; e++) { lg[e] = red[e][0] + gb[e]; mx = fmaxf(mx, lg[e]); }
#pragma unroll
        for (int e = 0; e < EE; e++) lg[e] = expf(lg[e] - mx);
        int i1 = 0;
#pragma unroll
        for (int e = 1; e < EE; e++) if (lg[e] > lg[i1]) i1 = e;
        int i2 = (i1 == 0) ? 1 : 0;
#pragma unroll
        for (int e = 0; e < EE; e++) if (e != i2 && e != i1 && lg[e] > lg[i2]) i2 = e;
        float p1 = lg[i1], p2 = lg[i2], inv = 1.f / (p1 + p2);
        g_tokExp[t * 2 + 0] = i1; g_tokW[t * 2 + 0] = p1 * inv;
        g_tokExp[t * 2 + 1] = i2; g_tokW[t * 2 + 1] = p2 * inv;
        atomicAdd(&g_count[i1], 1);
        atomicAdd(&g_count[i2], 1);
    }
}

// ================= fused scan + scatter (single block) =================
__global__ void scanscatter_kernel() {
    const int tid = threadIdx.x;
    if (tid == 0) {
        int off = 0;
#pragma unroll
        for (int e = 0; e < EE; e++) { g_offset[e] = off; g_cursor[e] = off; off += g_count[e]; }
    }
    __syncthreads();
    for (int t = tid; t < TT; t += 256) {
#pragma unroll
        for (int s = 0; s < 2; s++) {
            int e = g_tokExp[t * 2 + s];
            int p = atomicAdd(&g_cursor[e], 1);
            g_rowTok[p] = t;
            g_rowW[p]   = g_tokW[t * 2 + s];
        }
    }
}

// ================= GEMM1: block 128x64, pure fp16, 4-stage, 2 CTA/SM ==========
// stage: A(128r) + w1(64r) + w3(64r) = 10240 + 2*5120 = 20480
#define G1_STAGE (TILE128 + 2 * TILE64)
#define G1_SMEM  (1024 + 4 * G1_STAGE)     // 82944

__global__ void __launch_bounds__(256, 2)
gemm1_mma() {
    extern __shared__ char smem[];
    const int e   = blockIdx.z;
    const int cnt = g_count[e];
    const int off = g_offset[e];
    const int mB  = blockIdx.y * 128;
    if (mB >= cnt) return;
    const int valid = min(128, cnt - mB);
    const int nf0   = blockIdx.x * 64;
    const int tid   = threadIdx.x;
    const int wid   = tid >> 5, lane = tid & 31;

    int* tokSm = (int*)smem;
    if (tid < 128) tokSm[tid] = g_rowTok[off + mB + min(tid, valid - 1)];
    __syncthreads();

    const u32 sb = smem_u32(smem);
    const size_t wbase = (size_t)e * FF * DD + (size_t)nf0 * DD;

    const int lrow = tid >> 2, lch = tid & 3;    // lrow 0..63
    const int tok0 = tokSm[lrow], tok1 = tokSm[lrow + 64];

    auto load_stage = [&](int s, int k0) {
        u32 st = sb + 1024 + s * G1_STAGE;
        const u32 co = (u32)(lrow * ROWB + lch * 16);
        const size_t ko = (size_t)(k0 + lch * 8);
        cp16(st + co,             &g_xh[(size_t)tok0 * DD + ko]);
        cp16(st + co + 64 * ROWB, &g_xh[(size_t)tok1 * DD + ko]);
        const size_t go = wbase + (size_t)lrow * DD + ko;
        const u32 bb = st + TILE128;
        cp16(bb + co,          &g_w1h[go]);
        cp16(bb + TILE64 + co, &g_w3h[go]);
    };

    // warps: 4m x 2n, warp tile 32x32 (dual accumulators h1,h3)
    const int m_w = (wid >> 1) * 32, n_w = (wid & 1) * 32;
    const int lmat = lane >> 3, lr = lane & 7;
    const int aRow = m_w + (lmat & 1) * 8 + lr;
    const int aCol = (lmat >> 1) * 8;
    const int bRow = n_w + (lmat >> 1) * 8 + lr;
    const int bCol = (lmat & 1) * 8;

    float acc1[2][4][4], acc2[2][4][4];
#pragma unroll
    for (int mt = 0; mt < 2; mt++)
#pragma unroll
        for (int nt = 0; nt < 4; nt++)
#pragma unroll
            for (int q = 0; q < 4; q++) { acc1[mt][nt][q] = 0.f; acc2[mt][nt][q] = 0.f; }

    load_stage(0, 0);      cp_commit();
    load_stage(1, KT);     cp_commit();
    load_stage(2, 2 * KT); cp_commit();

    const int NK = DD / KT;   // 32
    for (int kt = 0; kt < NK; kt++) {
        cp_wait2();
        __syncthreads();
        if (kt + 3 < NK) load_stage((kt + 3) & 3, (kt + 3) * KT);
        cp_commit();
        const u32 st = sb + 1024 + (kt & 3) * G1_STAGE;
        const u32 bb = st + TILE128;
#pragma unroll
        for (int k16 = 0; k16 < KT; k16 += 16) {
            u32 aH[2][4];
#pragma unroll
            for (int mt = 0; mt < 2; mt++) {
                u32 ao = (u32)((aRow + mt * 16) * PITCH + k16 + aCol) * 2;
                ldsm4(st + ao, aH[mt]);
            }
#pragma unroll
            for (int p = 0; p < 2; p++) {
                u32 bo = (u32)((bRow + p * 16) * PITCH + k16 + bCol) * 2;
                u32 b1h[4], b3h[4];
                ldsm4(bb + bo,          b1h);
                ldsm4(bb + TILE64 + bo, b3h);
#pragma unroll
                for (int mt = 0; mt < 2; mt++)
#pragma unroll
                    for (int q = 0; q < 2; q++) {
                        mma16816(acc1[mt][p * 2 + q], aH[mt], &b1h[q * 2]);
                        mma16816(acc2[mt][p * 2 + q], aH[mt], &b3h[q * 2]);
                    }
            }
        }
    }

    // epilogue: silu(h1)*h3 -> fp16 -> global
    u32* outH = (u32*)g_acth;
#pragma unroll
    for (int mt = 0; mt < 2; mt++)
#pragma unroll
        for (int rh = 0; rh < 2; rh++) {
            int rowl = m_w + mt * 16 + rh * 8 + (lane >> 2);
            if (rowl < valid) {
                size_t base = (size_t)(off + mB + rowl) * FF + nf0;
#pragma unroll
                for (int nt = 0; nt < 4; nt++) {
                    float h0 = acc1[mt][nt][rh * 2 + 0];
                    float h1 = acc1[mt][nt][rh * 2 + 1];
                    float a0 = h0 * (1.f / (1.f + __expf(-h0))) * acc2[mt][nt][rh * 2 + 0];
                    float a1 = h1 * (1.f / (1.f + __expf(-h1))) * acc2[mt][nt][rh * 2 + 1];
                    __half2 hh;
                    hh.x = __float2half(a0);
                    hh.y = __float2half(a1);
                    size_t gi = (base + n_w + nt * 8 + (lane & 3) * 2) >> 1;
                    outH[gi] = *(u32*)&hh;
                }
            }
        }
}

// ================= GEMM2: block 128x128, pure fp16, 4-stage, 2 CTA/SM =========
// stage: A(128r) + w2(128r) = 2*10240 = 20480
#define G2_STAGE (2 * TILE128)
#define G2_SMEM  (1024 + 4 * G2_STAGE)     // 82944

__global__ void __launch_bounds__(256, 2)
gemm2_mma(float* __restrict__ out) {
    extern __shared__ char smem[];
    const int e   = blockIdx.z;
    const int cnt = g_count[e];
    const int off = g_offset[e];
    const int mB  = blockIdx.y * 128;
    if (mB >= cnt) return;
    const int valid = min(128, cnt - mB);
    const int nd0   = blockIdx.x * 128;
    const int tid   = threadIdx.x;
    const int wid   = tid >> 5, lane = tid & 31;

    const u32 sb = smem_u32(smem);
    const size_t wbase = (size_t)e * DD * FF + (size_t)nd0 * FF;

    const int lrow = tid >> 2, lch = tid & 3;    // lrow 0..63
    const int arow0 = off + mB + min(lrow, valid - 1);
    const int arow1 = off + mB + min(lrow + 64, valid - 1);

    auto load_stage = [&](int s, int k0) {
        u32 st = sb + 1024 + s * G2_STAGE;
        const u32 co = (u32)(lrow * ROWB + lch * 16);
        const size_t ko = (size_t)(k0 + lch * 8);
        cp16(st + co,             &g_acth[(size_t)arow0 * FF + ko]);
        cp16(st + co + 64 * ROWB, &g_acth[(size_t)arow1 * FF + ko]);
        const u32 bb = st + TILE128;
        cp16(bb + co,             &g_w2h[wbase + (size_t)lrow * FF + ko]);
        cp16(bb + co + 64 * ROWB, &g_w2h[wbase + (size_t)(lrow + 64) * FF + ko]);
    };

    // warps: 4m x 2n, warp tile 32x64
    const int m_w = (wid >> 1) * 32, n_w = (wid & 1) * 64;
    const int lmat = lane >> 3, lr = lane & 7;
    const int aRow = m_w + (lmat & 1) * 8 + lr;
    const int aCol = (lmat >> 1) * 8;
    const int bRow = n_w + (lmat >> 1) * 8 + lr;
    const int bCol = (lmat & 1) * 8;

    float acc[2][8][4];
#pragma unroll
    for (int mt = 0; mt < 2; mt++)
#pragma unroll
        for (int nt = 0; nt < 8; nt++)
#pragma unroll
            for (int q = 0; q < 4; q++) acc[mt][nt][q] = 0.f;

    load_stage(0, 0);      cp_commit();
    load_stage(1, KT);     cp_commit();
    load_stage(2, 2 * KT); cp_commit();

    const int NK = FF / KT;   // 128
    for (int kt = 0; kt < NK; kt++) {
        cp_wait2();
        __syncthreads();
        if (kt + 3 < NK) load_stage((kt + 3) & 3, (kt + 3) * KT);
        cp_commit();
        const u32 st = sb + 1024 + (kt & 3) * G2_STAGE;
        const u32 bb = st + TILE128;
#pragma unroll
        for (int k16 = 0; k16 < KT; k16 += 16) {
            u32 aH[2][4];
#pragma unroll
            for (int mt = 0; mt < 2; mt++) {
                u32 ao = (u32)((aRow + mt * 16) * PITCH + k16 + aCol) * 2;
                ldsm4(st + ao, aH[mt]);
            }
#pragma unroll
            for (int p = 0; p < 4; p++) {
                u32 bo = (u32)((bRow + p * 16) * PITCH + k16 + bCol) * 2;
                u32 bh[4];
                ldsm4(bb + bo, bh);
#pragma unroll
                for (int mt = 0; mt < 2; mt++)
#pragma unroll
                    for (int q = 0; q < 2; q++)
                        mma16816(acc[mt][p * 2 + q], aH[mt], &bh[q * 2]);
            }
        }
    }

    // epilogue: weighted atomic combine
#pragma unroll
    for (int mt = 0; mt < 2; mt++)
#pragma unroll
        for (int rh = 0; rh < 2; rh++) {
            int rowl = m_w + mt * 16 + rh * 8 + (lane >> 2);
            if (rowl < valid) {
                int gr = off + mB + rowl;
                int tok = g_rowTok[gr];
                float w = g_rowW[gr];
                float* op = &out[(size_t)tok * DD + nd0];
#pragma unroll
                for (int nt = 0; nt < 8; nt++) {
                    int c = n_w + nt * 8 + (lane & 3) * 2;
                    atomicAdd(op + c,     w * acc[mt][nt][rh * 2 + 0]);
                    atomicAdd(op + c + 1, w * acc[mt][nt][rh * 2 + 1]);
                }
            }
        }
}

// ================= host =================
extern "C" void kernel_launch(void* const* d_in, const int* in_sizes, int n_in,
                              void* d_out, int out_size) {
    const float* x  = (const float*)d_in[0];
    const float* gw = (const float*)d_in[1];
    const float* gb = (const float*)d_in[2];
    const float* w1 = (const float*)d_in[3];
    const float* w3 = (const float*)d_in[4];
    const float* w2 = (const float*)d_in[5];
    float* out = (float*)d_out;

    cudaFuncSetAttribute(gemm1_mma, cudaFuncAttributeMaxDynamicSharedMemorySize, G1_SMEM);
    cudaFuncSetAttribute(gemm2_mma, cudaFuncAttributeMaxDynamicSharedMemorySize, G2_SMEM);

    cudaMemsetAsync(out, 0, (size_t)out_size * sizeof(float), 0);

    const size_t totalChunks = (size_t)XC + 3 * (size_t)WC;
    split_all_kernel<<<(unsigned)((totalChunks + 255) / 256), 256>>>(x, w1, w3, w2);

    router_kernel<<<TT, 128>>>(x, gw, gb);
    scanscatter_kernel<<<1, 256>>>();

    dim3 g1(FF / 64, 32, EE);        // block 128 rows x 64 cols
    gemm1_mma<<<g1, 256, G1_SMEM>>>();
    dim3 g2(DD / 128, 32, EE);       // block 128 rows x 128 cols
    gemm2_mma<<<g2, 256, G2_SMEM>>>(out);
}

// round 9
// speedup vs baseline: 2.7177x; 1.0786x over previous
#include <cuda_runtime.h>
#include <cuda_fp16.h>

#define TT 4096
#define DD 1024
#define FF 4096
#define EE 8
#define NROWS (TT * 2)
#define NW   (EE * FF * DD)

typedef unsigned int u32;

// ================= device scratch (static) =================
__device__ __half g_xh[TT * DD];
__device__ __half g_w1h[NW];
__device__ __half g_w3h[NW];
__device__ __half g_w2h[NW];
__device__ __half g_acth[(size_t)NROWS * FF];

__device__ int   g_tokExp[TT * 2];
__device__ float g_tokW[TT * 2];
__device__ int   g_count[EE];
__device__ int   g_offset[EE];
__device__ int   g_cursor[EE];
__device__ int   g_rowTok[NROWS];
__device__ float g_rowW[NROWS];

// ================= PTX helpers (sm_80-generic only) =================
__device__ __forceinline__ u32 smem_u32(const void* p) {
    u32 a;
    asm("{ .reg .u64 t; cvta.to.shared.u64 t, %1; cvt.u32.u64 %0, t; }" : "=r"(a) : "l"(p));
    return a;
}
__device__ __forceinline__ void cp16(u32 dst, const void* src) {
    asm volatile("cp.async.cg.shared.global [%0], [%1], 16;" :: "r"(dst), "l"(src));
}
__device__ __forceinline__ void cp_commit() {
    asm volatile("cp.async.commit_group;" ::: "memory");
}
__device__ __forceinline__ void cp_wait1() {
    asm volatile("cp.async.wait_group 1;" ::: "memory");
}
__device__ __forceinline__ void ldsm4(u32 addr, u32* r) {
    asm volatile("ldmatrix.sync.aligned.m8n8.x4.shared.b16 {%0,%1,%2,%3}, [%4];"
        : "=r"(r[0]), "=r"(r[1]), "=r"(r[2]), "=r"(r[3]) : "r"(addr));
}
__device__ __forceinline__ void mma16816(float* d, const u32* a, const u32* b) {
    asm volatile(
        "mma.sync.aligned.m16n8k16.row.col.f32.f16.f16.f32 "
        "{%0,%1,%2,%3}, {%4,%5,%6,%7}, {%8,%9}, {%0,%1,%2,%3};"
        : "+f"(d[0]), "+f"(d[1]), "+f"(d[2]), "+f"(d[3])
        : "r"(a[0]), "r"(a[1]), "r"(a[2]), "r"(a[3]), "r"(b[0]), "r"(b[1]));
}

#define KT     64
#define PITCH  72                     // fp16 elems per smem row (144B: conflict-free)
#define ROWB   (PITCH * 2)            // 144 bytes per row
#define A_BYTES  (128 * ROWB)         // 18432
#define W_BYTES  (64 * ROWB)          // 9216

// ================= fused convert (+reset): all tensors -> fp16 ================
#define XC  (TT * DD / 4)
#define WC  (NW / 4)
__global__ void __launch_bounds__(256)
split_all_kernel(const float* __restrict__ x,  const float* __restrict__ w1,
                 const float* __restrict__ w3, const float* __restrict__ w2) {
    if (blockIdx.x == 0 && threadIdx.x < EE) g_count[threadIdx.x] = 0;
    size_t i = (size_t)blockIdx.x * 256 + threadIdx.x;
    const float* src;
    __half* dst;
    if (i < XC)               { src = x;  dst = g_xh; }
    else if (i < XC + WC)     { src = w1; dst = g_w1h; i -= XC; }
    else if (i < XC + 2 * WC) { src = w3; dst = g_w3h; i -= XC + WC; }
    else if (i < XC + 3 * WC) { src = w2; dst = g_w2h; i -= XC + 2 * WC; }
    else return;
    float4 v = ((const float4*)src)[i];
    __half2 h01, h23;
    h01.x = __float2half(v.x); h01.y = __float2half(v.y);
    h23.x = __float2half(v.z); h23.y = __float2half(v.w);
    ((uint2*)dst)[i] = make_uint2(*(u32*)&h01, *(u32*)&h23);
}

// ================= router =================
__global__ void router_kernel(const float* __restrict__ x,
                              const float* __restrict__ gw,
                              const float* __restrict__ gb) {
    const int t = blockIdx.x, tid = threadIdx.x;
    float acc[EE];
#pragma unroll
    for (int e = 0; e < EE; e++) acc[e] = 0.f;
    const float* xr = x + (size_t)t * DD;
    for (int d = tid; d < DD; d += 128) {
        float xv = xr[d];
#pragma unroll
        for (int e = 0; e < EE; e++) acc[e] += xv * gw[e * DD + d];
    }
    __shared__ float red[EE][128];
#pragma unroll
    for (int e = 0; e < EE; e++) red[e][tid] = acc[e];
    __syncthreads();
    for (int s = 64; s > 0; s >>= 1) {
        if (tid < s) {
#pragma unroll
            for (int e = 0; e < EE; e++) red[e][tid] += red[e][tid + s];
        }
        __syncthreads();
    }
    if (tid == 0) {
        float lg[EE]; float mx = -1e30f;
#pragma unroll
        for (int e = 0; e < EE; e++) { lg[e] = red[e][0] + gb[e]; mx = fmaxf(mx, lg[e]); }
#pragma unroll
        for (int e = 0; e < EE; e++) lg[e] = expf(lg[e] - mx);
        int i1 = 0;
#pragma unroll
        for (int e = 1; e < EE; e++) if (lg[e] > lg[i1]) i1 = e;
        int i2 = (i1 == 0) ? 1 : 0;
#pragma unroll
        for (int e = 0; e < EE; e++) if (e != i2 && e != i1 && lg[e] > lg[i2]) i2 = e;
        float p1 = lg[i1], p2 = lg[i2], inv = 1.f / (p1 + p2);
        g_tokExp[t * 2 + 0] = i1; g_tokW[t * 2 + 0] = p1 * inv;
        g_tokExp[t * 2 + 1] = i2; g_tokW[t * 2 + 1] = p2 * inv;
        atomicAdd(&g_count[i1], 1);
        atomicAdd(&g_count[i2], 1);
    }
}

// ================= fused scan + scatter (single block) =================
__global__ void scanscatter_kernel() {
    const int tid = threadIdx.x;
    if (tid == 0) {
        int off = 0;
#pragma unroll
        for (int e = 0; e < EE; e++) { g_offset[e] = off; g_cursor[e] = off; off += g_count[e]; }
    }
    __syncthreads();
    for (int t = tid; t < TT; t += 256) {
#pragma unroll
        for (int s = 0; s < 2; s++) {
            int e = g_tokExp[t * 2 + s];
            int p = atomicAdd(&g_cursor[e], 1);
            g_rowTok[p] = t;
            g_rowW[p]   = g_tokW[t * 2 + s];
        }
    }
}

// ================= GEMM1: block 128x64, fp16, KT=64, 3-stage, 2 CTA/SM ========
// stage: A(128r) + w1(64r) + w3(64r) = 18432 + 2*9216 = 36864
#define G1_STAGE (A_BYTES + 2 * W_BYTES)
#define G1_SMEM  (1024 + 3 * G1_STAGE)     // 111616

__global__ void __launch_bounds__(256, 2)
gemm1_mma() {
    extern __shared__ char smem[];
    const int e   = blockIdx.z;
    const int cnt = g_count[e];
    const int off = g_offset[e];
    const int mB  = blockIdx.y * 128;
    if (mB >= cnt) return;
    const int valid = min(128, cnt - mB);
    const int nf0   = blockIdx.x * 64;
    const int tid   = threadIdx.x;
    const int wid   = tid >> 5, lane = tid & 31;

    int* tokSm = (int*)smem;
    if (tid < 128) tokSm[tid] = g_rowTok[off + mB + min(tid, valid - 1)];
    __syncthreads();

    const u32 sb = smem_u32(smem);
    const size_t wbase = (size_t)e * FF * DD + (size_t)nf0 * DD;

    // load mapping: chunk i -> row=i>>3, ch=i&7 (16B); rows (tid>>3)+{0,32,64,96}
    const int lr0 = tid >> 3, lch = tid & 7;
    int tokR[4];
#pragma unroll
    for (int r = 0; r < 4; r++) tokR[r] = tokSm[lr0 + r * 32];

    auto load_stage = [&](int s, int k0) {
        u32 st = sb + 1024 + s * G1_STAGE;
        const size_t ko = (size_t)(k0 + lch * 8);
#pragma unroll
        for (int r = 0; r < 4; r++) {
            u32 co = (u32)((lr0 + r * 32) * ROWB + lch * 16);
            cp16(st + co, &g_xh[(size_t)tokR[r] * DD + ko]);
        }
        const u32 bb = st + A_BYTES;
#pragma unroll
        for (int r = 0; r < 2; r++) {
            int row = lr0 + r * 32;
            u32 co = (u32)(row * ROWB + lch * 16);
            size_t go = wbase + (size_t)row * DD + ko;
            cp16(bb + co,           &g_w1h[go]);
            cp16(bb + W_BYTES + co, &g_w3h[go]);
        }
    };

    // warps: 4m x 2n, warp tile 32x32 (dual accumulators h1,h3)
    const int m_w = (wid >> 1) * 32, n_w = (wid & 1) * 32;
    const int lmat = lane >> 3, lr = lane & 7;
    const int aRow = m_w + (lmat & 1) * 8 + lr;
    const int aCol = (lmat >> 1) * 8;
    const int bRow = n_w + (lmat >> 1) * 8 + lr;
    const int bCol = (lmat & 1) * 8;

    float acc1[2][4][4], acc2[2][4][4];
#pragma unroll
    for (int mt = 0; mt < 2; mt++)
#pragma unroll
        for (int nt = 0; nt < 4; nt++)
#pragma unroll
            for (int q = 0; q < 4; q++) { acc1[mt][nt][q] = 0.f; acc2[mt][nt][q] = 0.f; }

    load_stage(0, 0);  cp_commit();
    load_stage(1, KT); cp_commit();

    const int NK = DD / KT;   // 16
    for (int kt = 0; kt < NK; kt++) {
        cp_wait1();
        __syncthreads();
        if (kt + 2 < NK) load_stage((kt + 2) % 3, (kt + 2) * KT);
        cp_commit();
        const u32 st = sb + 1024 + (kt % 3) * G1_STAGE;
        const u32 bb = st + A_BYTES;
#pragma unroll
        for (int k16 = 0; k16 < KT; k16 += 16) {
            u32 aH[2][4];
#pragma unroll
            for (int mt = 0; mt < 2; mt++) {
                u32 ao = (u32)((aRow + mt * 16) * PITCH + k16 + aCol) * 2;
                ldsm4(st + ao, aH[mt]);
            }
#pragma unroll
            for (int p = 0; p < 2; p++) {
                u32 bo = (u32)((bRow + p * 16) * PITCH + k16 + bCol) * 2;
                u32 b1h[4], b3h[4];
                ldsm4(bb + bo,           b1h);
                ldsm4(bb + W_BYTES + bo, b3h);
#pragma unroll
                for (int mt = 0; mt < 2; mt++)
#pragma unroll
                    for (int q = 0; q < 2; q++) {
                        mma16816(acc1[mt][p * 2 + q], aH[mt], &b1h[q * 2]);
                        mma16816(acc2[mt][p * 2 + q], aH[mt], &b3h[q * 2]);
                    }
            }
        }
    }

    // epilogue: silu(h1)*h3 -> fp16 -> global
    u32* outH = (u32*)g_acth;
#pragma unroll
    for (int mt = 0; mt < 2; mt++)
#pragma unroll
        for (int rh = 0; rh < 2; rh++) {
            int rowl = m_w + mt * 16 + rh * 8 + (lane >> 2);
            if (rowl < valid) {
                size_t base = (size_t)(off + mB + rowl) * FF + nf0;
#pragma unroll
                for (int nt = 0; nt < 4; nt++) {
                    float h0 = acc1[mt][nt][rh * 2 + 0];
                    float h1 = acc1[mt][nt][rh * 2 + 1];
                    float a0 = h0 * (1.f / (1.f + __expf(-h0))) * acc2[mt][nt][rh * 2 + 0];
                    float a1 = h1 * (1.f / (1.f + __expf(-h1))) * acc2[mt][nt][rh * 2 + 1];
                    __half2 hh;
                    hh.x = __float2half(a0);
                    hh.y = __float2half(a1);
                    size_t gi = (base + n_w + nt * 8 + (lane & 3) * 2) >> 1;
                    outH[gi] = *(u32*)&hh;
                }
            }
        }
}

// ================= GEMM2: block 128x128, fp16, KT=64, 3-stage, 2 CTA/SM =======
// stage: A(128r) + w2(128r) = 2*18432 = 36864
#define G2_STAGE (2 * A_BYTES)
#define G2_SMEM  (1024 + 3 * G2_STAGE)     // 111616

__global__ void __launch_bounds__(256, 2)
gemm2_mma(float* __restrict__ out) {
    extern __shared__ char smem[];
    const int e   = blockIdx.z;
    const int cnt = g_count[e];
    const int off = g_offset[e];
    const int mB  = blockIdx.y * 128;
    if (mB >= cnt) return;
    const int valid = min(128, cnt - mB);
    const int nd0   = blockIdx.x * 128;
    const int tid   = threadIdx.x;
    const int wid   = tid >> 5, lane = tid & 31;

    const u32 sb = smem_u32(smem);
    const size_t wbase = (size_t)e * DD * FF + (size_t)nd0 * FF;

    const int lr0 = tid >> 3, lch = tid & 7;
    int arowR[4];
#pragma unroll
    for (int r = 0; r < 4; r++) arowR[r] = off + mB + min(lr0 + r * 32, valid - 1);

    auto load_stage = [&](int s, int k0) {
        u32 st = sb + 1024 + s * G2_STAGE;
        const size_t ko = (size_t)(k0 + lch * 8);
#pragma unroll
        for (int r = 0; r < 4; r++) {
            u32 co = (u32)((lr0 + r * 32) * ROWB + lch * 16);
            cp16(st + co, &g_acth[(size_t)arowR[r] * FF + ko]);
        }
        const u32 bb = st + A_BYTES;
#pragma unroll
        for (int r = 0; r < 4; r++) {
            int row = lr0 + r * 32;
            u32 co = (u32)(row * ROWB + lch * 16);
            cp16(bb + co, &g_w2h[wbase + (size_t)row * FF + ko]);
        }
    };

    // warps: 4m x 2n, warp tile 32x64
    const int m_w = (wid >> 1) * 32, n_w = (wid & 1) * 64;
    const int lmat = lane >> 3, lr = lane & 7;
    const int aRow = m_w + (lmat & 1) * 8 + lr;
    const int aCol = (lmat >> 1) * 8;
    const int bRow = n_w + (lmat >> 1) * 8 + lr;
    const int bCol = (lmat & 1) * 8;

    float acc[2][8][4];
#pragma unroll
    for (int mt = 0; mt < 2; mt++)
#pragma unroll
        for (int nt = 0; nt < 8; nt++)
#pragma unroll
            for (int q = 0; q < 4; q++) acc[mt][nt][q] = 0.f;

    load_stage(0, 0);  cp_commit();
    load_stage(1, KT); cp_commit();

    const int NK = FF / KT;   // 64
    for (int kt = 0; kt < NK; kt++) {
        cp_wait1();
        __syncthreads();
        if (kt + 2 < NK) load_stage((kt + 2) % 3, (kt + 2) * KT);
        cp_commit();
        const u32 st = sb + 1024 + (kt % 3) * G2_STAGE;
        const u32 bb = st + A_BYTES;
#pragma unroll
        for (int k16 = 0; k16 < KT; k16 += 16) {
            u32 aH[2][4];
#pragma unroll
            for (int mt = 0; mt < 2; mt++) {
                u32 ao = (u32)((aRow + mt * 16) * PITCH + k16 + aCol) * 2;
                ldsm4(st + ao, aH[mt]);
            }
#pragma unroll
            for (int p = 0; p < 4; p++) {
                u32 bo = (u32)((bRow + p * 16) * PITCH + k16 + bCol) * 2;
                u32 bh[4];
                ldsm4(bb + bo, bh);
#pragma unroll
                for (int mt = 0; mt < 2; mt++)
#pragma unroll
                    for (int q = 0; q < 2; q++)
                        mma16816(acc[mt][p * 2 + q], aH[mt], &bh[q * 2]);
            }
        }
    }

    // epilogue: weighted atomic combine
#pragma unroll
    for (int mt = 0; mt < 2; mt++)
#pragma unroll
        for (int rh = 0; rh < 2; rh++) {
            int rowl = m_w + mt * 16 + rh * 8 + (lane >> 2);
            if (rowl < valid) {
                int gr = off + mB + rowl;
                int tok = g_rowTok[gr];
                float w = g_rowW[gr];
                float* op = &out[(size_t)tok * DD + nd0];
#pragma unroll
                for (int nt = 0; nt < 8; nt++) {
                    int c = n_w + nt * 8 + (lane & 3) * 2;
                    atomicAdd(op + c,     w * acc[mt][nt][rh * 2 + 0]);
                    atomicAdd(op + c + 1, w * acc[mt][nt][rh * 2 + 1]);
                }
            }
        }
}

// ================= host =================
extern "C" void kernel_launch(void* const* d_in, const int* in_sizes, int n_in,
                              void* d_out, int out_size) {
    const float* x  = (const float*)d_in[0];
    const float* gw = (const float*)d_in[1];
    const float* gb = (const float*)d_in[2];
    const float* w1 = (const float*)d_in[3];
    const float* w3 = (const float*)d_in[4];
    const float* w2 = (const float*)d_in[5];
    float* out = (float*)d_out;

    cudaFuncSetAttribute(gemm1_mma, cudaFuncAttributeMaxDynamicSharedMemorySize, G1_SMEM);
    cudaFuncSetAttribute(gemm2_mma, cudaFuncAttributeMaxDynamicSharedMemorySize, G2_SMEM);

    cudaMemsetAsync(out, 0, (size_t)out_size * sizeof(float), 0);

    const size_t totalChunks = (size_t)XC + 3 * (size_t)WC;
    split_all_kernel<<<(unsigned)((totalChunks + 255) / 256), 256>>>(x, w1, w3, w2);

    router_kernel<<<TT, 128>>>(x, gw, gb);
    scanscatter_kernel<<<1, 256>>>();

    dim3 g1(FF / 64, 32, EE);        // block 128 rows x 64 cols
    gemm1_mma<<<g1, 256, G1_SMEM>>>();
    dim3 g2(DD / 128, 32, EE);       // block 128 rows x 128 cols
    gemm2_mma<<<g2, 256, G2_SMEM>>>(out);
}